// round 1
// baseline (speedup 1.0000x reference)
#include <cuda_runtime.h>
#include <cuda_bf16.h>
#include <math.h>

#define SDIM 768
#define CCH  128
#define NTOK (SDIM*SDIM)        // 589824 tokens
#define SELEM 75497472          // 128 * 589824

// Scratch (channel-major a/b, channel-major tri, token-major gate)
__device__ float g_a[SELEM];
__device__ float g_b[SELEM];
__device__ float g_tri[SELEM];
__device__ float g_gate[SELEM];

__device__ __forceinline__ float sigmoidf_(float v) {
    return 1.f / (1.f + __expf(-v));
}

// ---------------------------------------------------------------------------
// Kernel 1: fused LN(x) + dual projection (w_g_in, w_p_in) + sigmoid-gate mul
// Block: 256 thr, tile = 64 tokens x 64 output channels (of 256).
// Writes a (masked) and b channel-major: g_a[c*NTOK + t], g_b[c*NTOK + t].
// ---------------------------------------------------------------------------
__global__ void __launch_bounds__(256) proj_in_kernel(
    const float* __restrict__ x, const float* __restrict__ mask,
    const float* __restrict__ nw, const float* __restrict__ nb,
    const float* __restrict__ wg, const float* __restrict__ wp)
{
    extern __shared__ float sm[];
    float* xs  = sm;               // 64 x 132 (token-major, padded)
    float* wgs = sm + 64*132;      // 64 x 132 (c-major, k contiguous)
    float* wps = wgs + 64*132;
    __shared__ float mu[64], rsd[64];

    const int tid = threadIdx.x;
    const int t0  = blockIdx.x * 64;
    const int c0  = blockIdx.y * 64;

    // load x tile (64 tokens x 128 ch)
    for (int it = tid; it < 64*32; it += 256) {
        int row = it >> 5;
        int q   = (it & 31) << 2;
        float4 v = *(const float4*)(x + (size_t)(t0 + row)*CCH + q);
        *(float4*)&xs[row*132 + q] = v;
    }
    // load weight tiles, transposed to [c][k]
    for (int it = tid; it < 128*16; it += 256) {
        int k = it >> 4;
        int q = (it & 15) << 2;
        float4 vg = *(const float4*)(wg + (size_t)k*256 + c0 + q);
        float4 vp = *(const float4*)(wp + (size_t)k*256 + c0 + q);
        wgs[(q+0)*132 + k] = vg.x; wgs[(q+1)*132 + k] = vg.y;
        wgs[(q+2)*132 + k] = vg.z; wgs[(q+3)*132 + k] = vg.w;
        wps[(q+0)*132 + k] = vp.x; wps[(q+1)*132 + k] = vp.y;
        wps[(q+2)*132 + k] = vp.z; wps[(q+3)*132 + k] = vp.w;
    }
    __syncthreads();

    // LayerNorm per token (two-pass)
    if (tid < 64) {
        float s = 0.f;
        #pragma unroll 8
        for (int k = 0; k < 128; k++) s += xs[tid*132 + k];
        float m = s * (1.f/128.f);
        float v = 0.f;
        #pragma unroll 8
        for (int k = 0; k < 128; k++) { float d = xs[tid*132 + k] - m; v += d*d; }
        mu[tid]  = m;
        rsd[tid] = rsqrtf(v * (1.f/128.f) + 1e-5f);
    }
    __syncthreads();
    for (int it = tid; it < 64*128; it += 256) {
        int row = it >> 7, k = it & 127;
        xs[row*132 + k] = (xs[row*132 + k] - mu[row]) * rsd[row] * nw[k] + nb[k];
    }
    __syncthreads();

    // GEMM 64x64x128 (two accumulator sets: gate, proj)
    const int tx = tid & 15;   // token dim
    const int ty = tid >> 4;   // channel dim
    float accg[4][4], accp[4][4];
    #pragma unroll
    for (int i = 0; i < 4; i++)
        #pragma unroll
        for (int j = 0; j < 4; j++) { accg[i][j] = 0.f; accp[i][j] = 0.f; }

    #pragma unroll 4
    for (int k = 0; k < 128; k += 4) {
        float4 af[4], bg[4], bp[4];
        #pragma unroll
        for (int ii = 0; ii < 4; ii++)
            af[ii] = *(float4*)&xs[(ii*16 + tx)*132 + k];
        #pragma unroll
        for (int jj = 0; jj < 4; jj++) {
            bg[jj] = *(float4*)&wgs[(jj*16 + ty)*132 + k];
            bp[jj] = *(float4*)&wps[(jj*16 + ty)*132 + k];
        }
        #pragma unroll
        for (int ii = 0; ii < 4; ii++)
            #pragma unroll
            for (int jj = 0; jj < 4; jj++) {
                accg[ii][jj] += af[ii].x*bg[jj].x + af[ii].y*bg[jj].y
                              + af[ii].z*bg[jj].z + af[ii].w*bg[jj].w;
                accp[ii][jj] += af[ii].x*bp[jj].x + af[ii].y*bp[jj].y
                              + af[ii].z*bp[jj].z + af[ii].w*bp[jj].w;
            }
    }

    // epilogue: gp = sigmoid(g)*p ; split into a (masked) / b, channel-major
    #pragma unroll
    for (int ii = 0; ii < 4; ii++) {
        int t = t0 + ii*16 + tx;
        float mk = mask[t];
        #pragma unroll
        for (int jj = 0; jj < 4; jj++) {
            int c = c0 + jj*16 + ty;
            float val = sigmoidf_(accg[ii][jj]) * accp[ii][jj];
            if (c < 128) g_a[(size_t)c*NTOK + t] = val * mk;
            else         g_b[(size_t)(c-128)*NTOK + t] = val;
        }
    }
}

// ---------------------------------------------------------------------------
// Kernel 2: fused LN(x) + gate projection sigmoid(xn @ w_g_out), token-major.
// Block: 256 thr, tile = 64 tokens x 64 out channels (of 128).
// ---------------------------------------------------------------------------
__global__ void __launch_bounds__(256) proj_gate_kernel(
    const float* __restrict__ x,
    const float* __restrict__ nw, const float* __restrict__ nb,
    const float* __restrict__ wo)
{
    extern __shared__ float sm[];
    float* xs  = sm;               // 64 x 132
    float* wos = sm + 64*132;      // 64 x 132
    __shared__ float mu[64], rsd[64];

    const int tid = threadIdx.x;
    const int t0  = blockIdx.x * 64;
    const int c0  = blockIdx.y * 64;

    for (int it = tid; it < 64*32; it += 256) {
        int row = it >> 5;
        int q   = (it & 31) << 2;
        float4 v = *(const float4*)(x + (size_t)(t0 + row)*CCH + q);
        *(float4*)&xs[row*132 + q] = v;
    }
    for (int it = tid; it < 128*16; it += 256) {
        int k = it >> 4;
        int q = (it & 15) << 2;
        float4 vo = *(const float4*)(wo + (size_t)k*128 + c0 + q);
        wos[(q+0)*132 + k] = vo.x; wos[(q+1)*132 + k] = vo.y;
        wos[(q+2)*132 + k] = vo.z; wos[(q+3)*132 + k] = vo.w;
    }
    __syncthreads();

    if (tid < 64) {
        float s = 0.f;
        #pragma unroll 8
        for (int k = 0; k < 128; k++) s += xs[tid*132 + k];
        float m = s * (1.f/128.f);
        float v = 0.f;
        #pragma unroll 8
        for (int k = 0; k < 128; k++) { float d = xs[tid*132 + k] - m; v += d*d; }
        mu[tid]  = m;
        rsd[tid] = rsqrtf(v * (1.f/128.f) + 1e-5f);
    }
    __syncthreads();
    for (int it = tid; it < 64*128; it += 256) {
        int row = it >> 7, k = it & 127;
        xs[row*132 + k] = (xs[row*132 + k] - mu[row]) * rsd[row] * nw[k] + nb[k];
    }
    __syncthreads();

    // token-major output wants lanes varying over c: tx = c dim, ty = token dim
    const int tx = tid & 15;   // c dim
    const int ty = tid >> 4;   // token dim
    float acc[4][4];
    #pragma unroll
    for (int i = 0; i < 4; i++)
        #pragma unroll
        for (int j = 0; j < 4; j++) acc[i][j] = 0.f;

    #pragma unroll 4
    for (int k = 0; k < 128; k += 4) {
        float4 af[4], bf[4];
        #pragma unroll
        for (int jj = 0; jj < 4; jj++)
            af[jj] = *(float4*)&xs[(jj*16 + ty)*132 + k];
        #pragma unroll
        for (int ii = 0; ii < 4; ii++)
            bf[ii] = *(float4*)&wos[(ii*16 + tx)*132 + k];
        #pragma unroll
        for (int jj = 0; jj < 4; jj++)
            #pragma unroll
            for (int ii = 0; ii < 4; ii++)
                acc[jj][ii] += af[jj].x*bf[ii].x + af[jj].y*bf[ii].y
                             + af[jj].z*bf[ii].z + af[jj].w*bf[ii].w;
    }

    #pragma unroll
    for (int jj = 0; jj < 4; jj++) {
        int t = t0 + jj*16 + ty;
        #pragma unroll
        for (int ii = 0; ii < 4; ii++) {
            int c = c0 + ii*16 + tx;
            g_gate[(size_t)t*CCH + c] = sigmoidf_(acc[jj][ii]);
        }
    }
}

// ---------------------------------------------------------------------------
// Kernel 3: triangle einsum. Per channel c: tri[i,j] = sum_k A[i,k] * B[j,k]
// Grid (12, 12, 128). Block 256 thr, 64x64 tile, k chunks of 16.
// ---------------------------------------------------------------------------
__global__ void __launch_bounds__(256) tri_kernel()
{
    __shared__ float As[64*20], Bs[64*20];
    const int c  = blockIdx.z;
    const int i0 = blockIdx.y * 64;
    const int j0 = blockIdx.x * 64;
    const float* A = g_a + (size_t)c*NTOK;
    const float* B = g_b + (size_t)c*NTOK;

    const int tid = threadIdx.x;
    const int tx  = tid & 15;        // j dim
    const int ty  = tid >> 4;        // i dim
    const int r   = tid >> 2;        // load row
    const int q   = (tid & 3) << 2;  // load col (float4)

    float acc[4][4];
    #pragma unroll
    for (int i = 0; i < 4; i++)
        #pragma unroll
        for (int j = 0; j < 4; j++) acc[i][j] = 0.f;

    for (int kk = 0; kk < SDIM; kk += 16) {
        float4 va = *(const float4*)(A + (size_t)(i0 + r)*SDIM + kk + q);
        float4 vb = *(const float4*)(B + (size_t)(j0 + r)*SDIM + kk + q);
        __syncthreads();
        *(float4*)&As[r*20 + q] = va;
        *(float4*)&Bs[r*20 + q] = vb;
        __syncthreads();

        #pragma unroll
        for (int k4 = 0; k4 < 16; k4 += 4) {
            float4 af[4], bf[4];
            #pragma unroll
            for (int ii = 0; ii < 4; ii++)
                af[ii] = *(float4*)&As[(ii*16 + ty)*20 + k4];
            #pragma unroll
            for (int jj = 0; jj < 4; jj++)
                bf[jj] = *(float4*)&Bs[(jj*16 + tx)*20 + k4];
            #pragma unroll
            for (int ii = 0; ii < 4; ii++)
                #pragma unroll
                for (int jj = 0; jj < 4; jj++)
                    acc[ii][jj] += af[ii].x*bf[jj].x + af[ii].y*bf[jj].y
                                 + af[ii].z*bf[jj].z + af[ii].w*bf[jj].w;
        }
    }

    float* T = g_tri + (size_t)c*NTOK;
    #pragma unroll
    for (int ii = 0; ii < 4; ii++) {
        int i = i0 + ii*16 + ty;
        #pragma unroll
        for (int jj = 0; jj < 4; jj++)
            T[(size_t)i*SDIM + j0 + jj*16 + tx] = acc[ii][jj];
    }
}

// ---------------------------------------------------------------------------
// Kernel 4: LN(tri) over channels + @ w_p_out + multiply by gate -> out
// Block 256 thr per 64 tokens. tri read channel-major (coalesced over tokens).
// ---------------------------------------------------------------------------
__global__ void __launch_bounds__(256) out_kernel(
    const float* __restrict__ now, const float* __restrict__ nob,
    const float* __restrict__ wpo_g, float* __restrict__ out)
{
    extern __shared__ float sm[];
    float* trs = sm;              // 128 x 68  [ch][token]
    float* wpo = sm + 128*68;     // 128 x 128 [h][co]
    __shared__ float mu[64], rsd[64];

    const int tid = threadIdx.x;
    const int t0  = blockIdx.x * 64;

    for (int it = tid; it < 128*16; it += 256) {
        int ch = it >> 4;
        int q  = (it & 15) << 2;
        float4 v = *(const float4*)(g_tri + (size_t)ch*NTOK + t0 + q);
        *(float4*)&trs[ch*68 + q] = v;
    }
    for (int it = tid; it < 128*32; it += 256) {
        int h = it >> 5;
        int q = (it & 31) << 2;
        *(float4*)&wpo[h*128 + q] = *(const float4*)(wpo_g + (size_t)h*128 + q);
    }
    __syncthreads();

    // LN over channels per token (two-pass)
    if (tid < 64) {
        float s = 0.f;
        #pragma unroll 8
        for (int ch = 0; ch < 128; ch++) s += trs[ch*68 + tid];
        float m = s * (1.f/128.f);
        float v = 0.f;
        #pragma unroll 8
        for (int ch = 0; ch < 128; ch++) { float d = trs[ch*68 + tid] - m; v += d*d; }
        mu[tid]  = m;
        rsd[tid] = rsqrtf(v * (1.f/128.f) + 1e-5f);
    }
    __syncthreads();
    for (int it = tid; it < 128*64; it += 256) {
        int ch = it >> 6, t = it & 63;
        trs[ch*68 + t] = (trs[ch*68 + t] - mu[t]) * rsd[t] * now[ch] + nob[ch];
    }
    __syncthreads();

    // GEMM 64 tokens x 128 cout x 128
    const int tx = tid & 15;   // cout dim
    const int ty = tid >> 4;   // token dim
    float acc[4][8];
    #pragma unroll
    for (int i = 0; i < 4; i++)
        #pragma unroll
        for (int j = 0; j < 8; j++) acc[i][j] = 0.f;

    #pragma unroll 4
    for (int h = 0; h < 128; h++) {
        float af[4], bf[8];
        #pragma unroll
        for (int ii = 0; ii < 4; ii++) af[ii] = trs[h*68 + ii*16 + ty];
        #pragma unroll
        for (int jj = 0; jj < 8; jj++) bf[jj] = wpo[h*128 + jj*16 + tx];
        #pragma unroll
        for (int ii = 0; ii < 4; ii++)
            #pragma unroll
            for (int jj = 0; jj < 8; jj++)
                acc[ii][jj] += af[ii] * bf[jj];
    }

    #pragma unroll
    for (int ii = 0; ii < 4; ii++) {
        int t = t0 + ii*16 + ty;
        #pragma unroll
        for (int jj = 0; jj < 8; jj++) {
            int co = jj*16 + tx;
            out[(size_t)t*CCH + co] = acc[ii][jj] * g_gate[(size_t)t*CCH + co];
        }
    }
}

// ---------------------------------------------------------------------------
extern "C" void kernel_launch(void* const* d_in, const int* in_sizes, int n_in,
                              void* d_out, int out_size)
{
    const float* x    = (const float*)d_in[0];
    const float* mask = (const float*)d_in[1];
    const float* niw  = (const float*)d_in[2];
    const float* nib  = (const float*)d_in[3];
    const float* wgi  = (const float*)d_in[4];
    const float* wpi  = (const float*)d_in[5];
    const float* now  = (const float*)d_in[6];
    const float* nob  = (const float*)d_in[7];
    const float* wgo  = (const float*)d_in[8];
    const float* wpo  = (const float*)d_in[9];
    float* out = (float*)d_out;

    const int smem_proj = (3*64*132) * 4;              // 101376 B
    const int smem_gate = (2*64*132) * 4;              //  67584 B
    const int smem_out  = (128*68 + 128*128) * 4;      // 100352 B
    cudaFuncSetAttribute(proj_in_kernel,
        cudaFuncAttributeMaxDynamicSharedMemorySize, smem_proj);
    cudaFuncSetAttribute(proj_gate_kernel,
        cudaFuncAttributeMaxDynamicSharedMemorySize, smem_gate);
    cudaFuncSetAttribute(out_kernel,
        cudaFuncAttributeMaxDynamicSharedMemorySize, smem_out);

    proj_in_kernel<<<dim3(NTOK/64, 4), 256, smem_proj>>>(x, mask, niw, nib, wgi, wpi);
    proj_gate_kernel<<<dim3(NTOK/64, 2), 256, smem_gate>>>(x, niw, nib, wgo);
    tri_kernel<<<dim3(12, 12, 128), 256>>>();
    out_kernel<<<NTOK/64, 256, smem_out>>>(now, nob, wpo, out);
}

// round 3
// speedup vs baseline: 1.4220x; 1.4220x over previous
#include <cuda_runtime.h>
#include <cuda_bf16.h>
#include <math.h>
#include <stdint.h>

#define SDIM 768
#define CCH  128
#define NTOK (SDIM*SDIM)        // 589824 tokens
#define SELEM 75497472          // 128 * 589824

// Scratch: channel-major split-bf16 a/b, channel-major tri (fp32), token-major gate
__device__ __nv_bfloat16 g_ahi[SELEM];
__device__ __nv_bfloat16 g_alo[SELEM];
__device__ __nv_bfloat16 g_bhi[SELEM];
__device__ __nv_bfloat16 g_blo[SELEM];
__device__ float g_tri[SELEM];
__device__ float g_gate[SELEM];

__device__ __forceinline__ float sigmoidf_(float v) {
    return 1.f / (1.f + __expf(-v));
}

__device__ __forceinline__ uint32_t smem_u32(const void* p) {
    uint32_t a;
    asm("{ .reg .u64 t; cvta.to.shared.u64 t, %1; cvt.u32.u64 %0, t; }"
        : "=r"(a) : "l"(p));
    return a;
}
#define CP_ASYNC16(d, s)  asm volatile("cp.async.cg.shared.global [%0], [%1], 16;" :: "r"(d), "l"(s))
#define CP_COMMIT()       asm volatile("cp.async.commit_group;" ::: "memory")
#define CP_WAIT0()        asm volatile("cp.async.wait_group 0;" ::: "memory")
#define CP_WAIT1()        asm volatile("cp.async.wait_group 1;" ::: "memory")

__device__ __forceinline__ void ldsm4(uint32_t* r, uint32_t addr) {
    asm volatile("ldmatrix.sync.aligned.m8n8.x4.shared.b16 {%0,%1,%2,%3}, [%4];"
        : "=r"(r[0]), "=r"(r[1]), "=r"(r[2]), "=r"(r[3]) : "r"(addr));
}
__device__ __forceinline__ void mma16816(float* d, const uint32_t* a, const uint32_t* b) {
    asm volatile("mma.sync.aligned.m16n8k16.row.col.f32.bf16.bf16.f32 "
        "{%0,%1,%2,%3}, {%4,%5,%6,%7}, {%8,%9}, {%0,%1,%2,%3};"
        : "+f"(d[0]), "+f"(d[1]), "+f"(d[2]), "+f"(d[3])
        : "r"(a[0]), "r"(a[1]), "r"(a[2]), "r"(a[3]), "r"(b[0]), "r"(b[1]));
}

// ---------------------------------------------------------------------------
// Kernel 1: fused LN(x) + dual projection + sigmoid-gate mul.
// Writes a (masked) / b as channel-major split bf16 (hi, lo).
// ---------------------------------------------------------------------------
__global__ void __launch_bounds__(256) proj_in_kernel(
    const float* __restrict__ x, const float* __restrict__ mask,
    const float* __restrict__ nw, const float* __restrict__ nb,
    const float* __restrict__ wg, const float* __restrict__ wp)
{
    extern __shared__ float sm[];
    float* xs  = sm;               // 64 x 132
    float* wgs = sm + 64*132;
    float* wps = wgs + 64*132;
    __shared__ float mu[64], rsd[64];

    const int tid = threadIdx.x;
    const int t0  = blockIdx.x * 64;
    const int c0  = blockIdx.y * 64;

    for (int it = tid; it < 64*32; it += 256) {
        int row = it >> 5;
        int q   = (it & 31) << 2;
        float4 v = *(const float4*)(x + (size_t)(t0 + row)*CCH + q);
        *(float4*)&xs[row*132 + q] = v;
    }
    for (int it = tid; it < 128*16; it += 256) {
        int k = it >> 4;
        int q = (it & 15) << 2;
        float4 vg = *(const float4*)(wg + (size_t)k*256 + c0 + q);
        float4 vp = *(const float4*)(wp + (size_t)k*256 + c0 + q);
        wgs[(q+0)*132 + k] = vg.x; wgs[(q+1)*132 + k] = vg.y;
        wgs[(q+2)*132 + k] = vg.z; wgs[(q+3)*132 + k] = vg.w;
        wps[(q+0)*132 + k] = vp.x; wps[(q+1)*132 + k] = vp.y;
        wps[(q+2)*132 + k] = vp.z; wps[(q+3)*132 + k] = vp.w;
    }
    __syncthreads();

    if (tid < 64) {
        float s = 0.f;
        #pragma unroll 8
        for (int k = 0; k < 128; k++) s += xs[tid*132 + k];
        float m = s * (1.f/128.f);
        float v = 0.f;
        #pragma unroll 8
        for (int k = 0; k < 128; k++) { float d = xs[tid*132 + k] - m; v += d*d; }
        mu[tid]  = m;
        rsd[tid] = rsqrtf(v * (1.f/128.f) + 1e-5f);
    }
    __syncthreads();
    for (int it = tid; it < 64*128; it += 256) {
        int row = it >> 7, k = it & 127;
        xs[row*132 + k] = (xs[row*132 + k] - mu[row]) * rsd[row] * nw[k] + nb[k];
    }
    __syncthreads();

    const int tx = tid & 15;   // token dim
    const int ty = tid >> 4;   // channel dim
    float accg[4][4], accp[4][4];
    #pragma unroll
    for (int i = 0; i < 4; i++)
        #pragma unroll
        for (int j = 0; j < 4; j++) { accg[i][j] = 0.f; accp[i][j] = 0.f; }

    #pragma unroll 4
    for (int k = 0; k < 128; k += 4) {
        float4 af[4], bg[4], bp[4];
        #pragma unroll
        for (int ii = 0; ii < 4; ii++)
            af[ii] = *(float4*)&xs[(ii*16 + tx)*132 + k];
        #pragma unroll
        for (int jj = 0; jj < 4; jj++) {
            bg[jj] = *(float4*)&wgs[(jj*16 + ty)*132 + k];
            bp[jj] = *(float4*)&wps[(jj*16 + ty)*132 + k];
        }
        #pragma unroll
        for (int ii = 0; ii < 4; ii++)
            #pragma unroll
            for (int jj = 0; jj < 4; jj++) {
                accg[ii][jj] += af[ii].x*bg[jj].x + af[ii].y*bg[jj].y
                              + af[ii].z*bg[jj].z + af[ii].w*bg[jj].w;
                accp[ii][jj] += af[ii].x*bp[jj].x + af[ii].y*bp[jj].y
                              + af[ii].z*bp[jj].z + af[ii].w*bp[jj].w;
            }
    }

    #pragma unroll
    for (int ii = 0; ii < 4; ii++) {
        int t = t0 + ii*16 + tx;
        float mk = mask[t];
        #pragma unroll
        for (int jj = 0; jj < 4; jj++) {
            int c = c0 + jj*16 + ty;
            float val = sigmoidf_(accg[ii][jj]) * accp[ii][jj];
            if (c < 128) {
                float av = val * mk;
                __nv_bfloat16 h = __float2bfloat16(av);
                g_ahi[(size_t)c*NTOK + t] = h;
                g_alo[(size_t)c*NTOK + t] = __float2bfloat16(av - __bfloat162float(h));
            } else {
                __nv_bfloat16 h = __float2bfloat16(val);
                g_bhi[(size_t)(c-128)*NTOK + t] = h;
                g_blo[(size_t)(c-128)*NTOK + t] = __float2bfloat16(val - __bfloat162float(h));
            }
        }
    }
}

// ---------------------------------------------------------------------------
// Kernel 2: fused LN(x) + sigmoid(xn @ w_g_out), token-major.
// ---------------------------------------------------------------------------
__global__ void __launch_bounds__(256) proj_gate_kernel(
    const float* __restrict__ x,
    const float* __restrict__ nw, const float* __restrict__ nb,
    const float* __restrict__ wo)
{
    extern __shared__ float sm[];
    float* xs  = sm;
    float* wos = sm + 64*132;
    __shared__ float mu[64], rsd[64];

    const int tid = threadIdx.x;
    const int t0  = blockIdx.x * 64;
    const int c0  = blockIdx.y * 64;

    for (int it = tid; it < 64*32; it += 256) {
        int row = it >> 5;
        int q   = (it & 31) << 2;
        float4 v = *(const float4*)(x + (size_t)(t0 + row)*CCH + q);
        *(float4*)&xs[row*132 + q] = v;
    }
    for (int it = tid; it < 128*16; it += 256) {
        int k = it >> 4;
        int q = (it & 15) << 2;
        float4 vo = *(const float4*)(wo + (size_t)k*128 + c0 + q);
        wos[(q+0)*132 + k] = vo.x; wos[(q+1)*132 + k] = vo.y;
        wos[(q+2)*132 + k] = vo.z; wos[(q+3)*132 + k] = vo.w;
    }
    __syncthreads();

    if (tid < 64) {
        float s = 0.f;
        #pragma unroll 8
        for (int k = 0; k < 128; k++) s += xs[tid*132 + k];
        float m = s * (1.f/128.f);
        float v = 0.f;
        #pragma unroll 8
        for (int k = 0; k < 128; k++) { float d = xs[tid*132 + k] - m; v += d*d; }
        mu[tid]  = m;
        rsd[tid] = rsqrtf(v * (1.f/128.f) + 1e-5f);
    }
    __syncthreads();
    for (int it = tid; it < 64*128; it += 256) {
        int row = it >> 7, k = it & 127;
        xs[row*132 + k] = (xs[row*132 + k] - mu[row]) * rsd[row] * nw[k] + nb[k];
    }
    __syncthreads();

    const int tx = tid & 15;   // c dim
    const int ty = tid >> 4;   // token dim
    float acc[4][4];
    #pragma unroll
    for (int i = 0; i < 4; i++)
        #pragma unroll
        for (int j = 0; j < 4; j++) acc[i][j] = 0.f;

    #pragma unroll 4
    for (int k = 0; k < 128; k += 4) {
        float4 af[4], bf[4];
        #pragma unroll
        for (int jj = 0; jj < 4; jj++)
            af[jj] = *(float4*)&xs[(jj*16 + ty)*132 + k];
        #pragma unroll
        for (int ii = 0; ii < 4; ii++)
            bf[ii] = *(float4*)&wos[(ii*16 + tx)*132 + k];
        #pragma unroll
        for (int jj = 0; jj < 4; jj++)
            #pragma unroll
            for (int ii = 0; ii < 4; ii++)
                acc[jj][ii] += af[jj].x*bf[ii].x + af[jj].y*bf[ii].y
                             + af[jj].z*bf[ii].z + af[jj].w*bf[ii].w;
    }

    #pragma unroll
    for (int jj = 0; jj < 4; jj++) {
        int t = t0 + jj*16 + ty;
        #pragma unroll
        for (int ii = 0; ii < 4; ii++) {
            int c = c0 + ii*16 + tx;
            g_gate[(size_t)t*CCH + c] = sigmoidf_(acc[jj][ii]);
        }
    }
}

// ---------------------------------------------------------------------------
// Kernel 3: triangle einsum via mma.sync bf16 with split-bf16 (3 passes).
// Per CTA: channel c, 128x128 tile, K=768 in 12 chunks of 64, cp.async
// double-buffered. 8 warps (2m x 4n), warp tile 64x32.
// Grid: (36, 128). Block: 256 threads.
// ---------------------------------------------------------------------------
#define ROWB   144                  // 64 bf16 data + 8 pad = 72 bf16 = 144 B
#define TILEB  (128*ROWB)           // 18432 B per operand tile
#define CHUNKB (4*TILEB)            // Ah, Al, Bh, Bl

__device__ __forceinline__ void tri_load_chunk(
    uint32_t sbuf, const __nv_bfloat16* s0, const __nv_bfloat16* s1,
    const __nv_bfloat16* s2, const __nv_bfloat16* s3, int kk, int tid)
{
    const __nv_bfloat16* srcs[4] = {s0, s1, s2, s3};
    #pragma unroll
    for (int rep = 0; rep < 16; rep++) {
        int it   = tid + rep*256;              // 0..4095
        int tile = it >> 10;
        int row  = (it >> 3) & 127;
        int q8   = it & 7;
        const __nv_bfloat16* gp = srcs[tile] + (size_t)row*SDIM + kk + q8*8;
        CP_ASYNC16(sbuf + tile*TILEB + row*ROWB + q8*16, gp);
    }
}

__global__ void __launch_bounds__(256) tri_mma_kernel()
{
    extern __shared__ char dynsm[];
    const uint32_t base = smem_u32(dynsm);

    const int tid  = threadIdx.x;
    const int wid  = tid >> 5;
    const int lane = tid & 31;
    const int wm   = wid >> 2;          // 0..1  (m)
    const int wn   = wid & 3;           // 0..3  (n)
    const int m_base = wm * 64;
    const int n_base = wn * 32;

    const int c  = blockIdx.y;
    const int i0 = (blockIdx.x / 6) * 128;
    const int j0 = (blockIdx.x % 6) * 128;

    const __nv_bfloat16* sAh = g_ahi + (size_t)c*NTOK + (size_t)i0*SDIM;
    const __nv_bfloat16* sAl = g_alo + (size_t)c*NTOK + (size_t)i0*SDIM;
    const __nv_bfloat16* sBh = g_bhi + (size_t)c*NTOK + (size_t)j0*SDIM;
    const __nv_bfloat16* sBl = g_blo + (size_t)c*NTOK + (size_t)j0*SDIM;

    float acc[4][4][4];
    #pragma unroll
    for (int mt = 0; mt < 4; mt++)
        #pragma unroll
        for (int nt = 0; nt < 4; nt++)
            #pragma unroll
            for (int r = 0; r < 4; r++) acc[mt][nt][r] = 0.f;

    // precomputed ldmatrix lane addressing
    const int a_row  = lane & 15;
    const int a_half = lane >> 4;                 // 0/1 -> k 0-7 / 8-15
    const int b_quad = lane >> 3;                 // 0..3
    const int b_row  = (b_quad >> 1) * 8 + (lane & 7);
    const int b_half = b_quad & 1;

    tri_load_chunk(base, sAh, sAl, sBh, sBl, 0, tid);
    CP_COMMIT();

    for (int n = 0; n < 12; n++) {
        if (n < 11) {
            tri_load_chunk(base + ((n+1)&1)*CHUNKB, sAh, sAl, sBh, sBl, (n+1)*64, tid);
            CP_COMMIT();
            CP_WAIT1();
        } else {
            CP_WAIT0();
        }
        __syncthreads();

        const uint32_t sb = base + (n&1)*CHUNKB;
        #pragma unroll
        for (int ks = 0; ks < 4; ks++) {
            uint32_t Ah[4][4], Al[4][4], Bh[4][2], Bl[4][2];
            const uint32_t koff = ks*32;
            #pragma unroll
            for (int mt = 0; mt < 4; mt++) {
                uint32_t r = (m_base + mt*16 + a_row)*ROWB + koff + a_half*16;
                ldsm4(Ah[mt], sb + 0*TILEB + r);
                ldsm4(Al[mt], sb + 1*TILEB + r);
            }
            #pragma unroll
            for (int p = 0; p < 2; p++) {
                uint32_t r = (n_base + p*16 + b_row)*ROWB + koff + b_half*16;
                uint32_t th[4], tl[4];
                ldsm4(th, sb + 2*TILEB + r);
                ldsm4(tl, sb + 3*TILEB + r);
                Bh[2*p][0]   = th[0]; Bh[2*p][1]   = th[1];
                Bh[2*p+1][0] = th[2]; Bh[2*p+1][1] = th[3];
                Bl[2*p][0]   = tl[0]; Bl[2*p][1]   = tl[1];
                Bl[2*p+1][0] = tl[2]; Bl[2*p+1][1] = tl[3];
            }
            #pragma unroll
            for (int mt = 0; mt < 4; mt++)
                #pragma unroll
                for (int nt = 0; nt < 4; nt++)
                    mma16816(acc[mt][nt], Ah[mt], Bh[nt]);
            #pragma unroll
            for (int mt = 0; mt < 4; mt++)
                #pragma unroll
                for (int nt = 0; nt < 4; nt++)
                    mma16816(acc[mt][nt], Ah[mt], Bl[nt]);
            #pragma unroll
            for (int mt = 0; mt < 4; mt++)
                #pragma unroll
                for (int nt = 0; nt < 4; nt++)
                    mma16816(acc[mt][nt], Al[mt], Bh[nt]);
        }
        __syncthreads();
    }

    // epilogue: direct float2 stores
    float* T = g_tri + (size_t)c*NTOK;
    const int er = i0 + m_base + (lane >> 2);
    const int ec = j0 + n_base + (lane & 3)*2;
    #pragma unroll
    for (int mt = 0; mt < 4; mt++) {
        #pragma unroll
        for (int nt = 0; nt < 4; nt++) {
            int rr = er + mt*16;
            int cc = ec + nt*8;
            *(float2*)&T[(size_t)rr*SDIM + cc]     = make_float2(acc[mt][nt][0], acc[mt][nt][1]);
            *(float2*)&T[(size_t)(rr+8)*SDIM + cc] = make_float2(acc[mt][nt][2], acc[mt][nt][3]);
        }
    }
}

// ---------------------------------------------------------------------------
// Kernel 4: LN(tri) over channels + @ w_p_out + gate mul -> out
// ---------------------------------------------------------------------------
__global__ void __launch_bounds__(256) out_kernel(
    const float* __restrict__ now, const float* __restrict__ nob,
    const float* __restrict__ wpo_g, float* __restrict__ out)
{
    extern __shared__ float sm[];
    float* trs = sm;              // 128 x 68  [ch][token]
    float* wpo = sm + 128*68;     // 128 x 128 [h][co]
    __shared__ float mu[64], rsd[64];

    const int tid = threadIdx.x;
    const int t0  = blockIdx.x * 64;

    for (int it = tid; it < 128*16; it += 256) {
        int ch = it >> 4;
        int q  = (it & 15) << 2;
        float4 v = *(const float4*)(g_tri + (size_t)ch*NTOK + t0 + q);
        *(float4*)&trs[ch*68 + q] = v;
    }
    for (int it = tid; it < 128*32; it += 256) {
        int h = it >> 5;
        int q = (it & 31) << 2;
        *(float4*)&wpo[h*128 + q] = *(const float4*)(wpo_g + (size_t)h*128 + q);
    }
    __syncthreads();

    if (tid < 64) {
        float s = 0.f;
        #pragma unroll 8
        for (int ch = 0; ch < 128; ch++) s += trs[ch*68 + tid];
        float m = s * (1.f/128.f);
        float v = 0.f;
        #pragma unroll 8
        for (int ch = 0; ch < 128; ch++) { float d = trs[ch*68 + tid] - m; v += d*d; }
        mu[tid]  = m;
        rsd[tid] = rsqrtf(v * (1.f/128.f) + 1e-5f);
    }
    __syncthreads();
    for (int it = tid; it < 128*64; it += 256) {
        int ch = it >> 6, t = it & 63;
        trs[ch*68 + t] = (trs[ch*68 + t] - mu[t]) * rsd[t] * now[ch] + nob[ch];
    }
    __syncthreads();

    const int tx = tid & 15;   // cout dim
    const int ty = tid >> 4;   // token dim
    float acc[4][8];
    #pragma unroll
    for (int i = 0; i < 4; i++)
        #pragma unroll
        for (int j = 0; j < 8; j++) acc[i][j] = 0.f;

    #pragma unroll 4
    for (int h = 0; h < 128; h++) {
        float af[4], bf[8];
        #pragma unroll
        for (int ii = 0; ii < 4; ii++) af[ii] = trs[h*68 + ii*16 + ty];
        #pragma unroll
        for (int jj = 0; jj < 8; jj++) bf[jj] = wpo[h*128 + jj*16 + tx];
        #pragma unroll
        for (int ii = 0; ii < 4; ii++)
            #pragma unroll
            for (int jj = 0; jj < 8; jj++)
                acc[ii][jj] += af[ii] * bf[jj];
    }

    #pragma unroll
    for (int ii = 0; ii < 4; ii++) {
        int t = t0 + ii*16 + ty;
        #pragma unroll
        for (int jj = 0; jj < 8; jj++) {
            int co = jj*16 + tx;
            out[(size_t)t*CCH + co] = acc[ii][jj] * g_gate[(size_t)t*CCH + co];
        }
    }
}

// ---------------------------------------------------------------------------
extern "C" void kernel_launch(void* const* d_in, const int* in_sizes, int n_in,
                              void* d_out, int out_size)
{
    const float* x    = (const float*)d_in[0];
    const float* mask = (const float*)d_in[1];
    const float* niw  = (const float*)d_in[2];
    const float* nib  = (const float*)d_in[3];
    const float* wgi  = (const float*)d_in[4];
    const float* wpi  = (const float*)d_in[5];
    const float* now  = (const float*)d_in[6];
    const float* nob  = (const float*)d_in[7];
    const float* wgo  = (const float*)d_in[8];
    const float* wpo  = (const float*)d_in[9];
    float* out = (float*)d_out;

    const int smem_proj = (3*64*132) * 4;
    const int smem_gate = (2*64*132) * 4;
    const int smem_out  = (128*68 + 128*128) * 4;
    const int smem_tri  = 2*CHUNKB;                    // 147456 B
    cudaFuncSetAttribute(proj_in_kernel,
        cudaFuncAttributeMaxDynamicSharedMemorySize, smem_proj);
    cudaFuncSetAttribute(proj_gate_kernel,
        cudaFuncAttributeMaxDynamicSharedMemorySize, smem_gate);
    cudaFuncSetAttribute(out_kernel,
        cudaFuncAttributeMaxDynamicSharedMemorySize, smem_out);
    cudaFuncSetAttribute(tri_mma_kernel,
        cudaFuncAttributeMaxDynamicSharedMemorySize, smem_tri);

    proj_in_kernel<<<dim3(NTOK/64, 4), 256, smem_proj>>>(x, mask, niw, nib, wgi, wpi);
    proj_gate_kernel<<<dim3(NTOK/64, 2), 256, smem_gate>>>(x, niw, nib, wgo);
    tri_mma_kernel<<<dim3(36, 128), 256, smem_tri>>>();
    out_kernel<<<NTOK/64, 256, smem_out>>>(now, nob, wpo, out);
}

// round 4
// speedup vs baseline: 2.4153x; 1.6985x over previous
#include <cuda_runtime.h>
#include <cuda_bf16.h>
#include <math.h>
#include <stdint.h>

#define SDIM 768
#define CCH  128
#define NTOK (SDIM*SDIM)        // 589824 tokens
#define SELEM 75497472          // 128 * 589824

// Scratch
__device__ __nv_bfloat16 g_ahi[SELEM];
__device__ __nv_bfloat16 g_alo[SELEM];
__device__ __nv_bfloat16 g_bhi[SELEM];
__device__ __nv_bfloat16 g_blo[SELEM];
__device__ float g_tri[SELEM];
__device__ float g_gate[SELEM];

// Prepped split-bf16 weights, [n][k] layout (k contiguous, 128 per row)
__device__ __nv_bfloat16 g_wgih[256*128], g_wgil[256*128];
__device__ __nv_bfloat16 g_wpih[256*128], g_wpil[256*128];
__device__ __nv_bfloat16 g_wgoh[128*128], g_wgol[128*128];
__device__ __nv_bfloat16 g_wpoh[128*128], g_wpol[128*128];

__device__ __forceinline__ float sigmoidf_(float v) {
    return 1.f / (1.f + __expf(-v));
}
__device__ __forceinline__ uint32_t smem_u32(const void* p) {
    uint32_t a;
    asm("{ .reg .u64 t; cvta.to.shared.u64 t, %1; cvt.u32.u64 %0, t; }"
        : "=r"(a) : "l"(p));
    return a;
}
#define CP_ASYNC16(d, s)  asm volatile("cp.async.cg.shared.global [%0], [%1], 16;" :: "r"(d), "l"(s))
#define CP_COMMIT()       asm volatile("cp.async.commit_group;" ::: "memory")
#define CP_WAIT0()        asm volatile("cp.async.wait_group 0;" ::: "memory")
#define CP_WAIT1()        asm volatile("cp.async.wait_group 1;" ::: "memory")

__device__ __forceinline__ void ldsm4(uint32_t* r, uint32_t addr) {
    asm volatile("ldmatrix.sync.aligned.m8n8.x4.shared.b16 {%0,%1,%2,%3}, [%4];"
        : "=r"(r[0]), "=r"(r[1]), "=r"(r[2]), "=r"(r[3]) : "r"(addr));
}
__device__ __forceinline__ void mma16816(float* d, const uint32_t* a, const uint32_t* b) {
    asm volatile("mma.sync.aligned.m16n8k16.row.col.f32.bf16.bf16.f32 "
        "{%0,%1,%2,%3}, {%4,%5,%6,%7}, {%8,%9}, {%0,%1,%2,%3};"
        : "+f"(d[0]), "+f"(d[1]), "+f"(d[2]), "+f"(d[3])
        : "r"(a[0]), "r"(a[1]), "r"(a[2]), "r"(a[3]), "r"(b[0]), "r"(b[1]));
}

// ---------------------------------------------------------------------------
// Kernel 0: weight prep — transpose + split to bf16 hi/lo, [n][k].
// ---------------------------------------------------------------------------
__global__ void __launch_bounds__(256) prep_w_kernel(
    const float* __restrict__ wgi, const float* __restrict__ wpi,
    const float* __restrict__ wgo, const float* __restrict__ wpo)
{
    int idx = blockIdx.x*256 + threadIdx.x;   // 0..32767
    int n = idx >> 7, k = idx & 127;

    float v = wgi[k*256 + n];
    __nv_bfloat16 h = __float2bfloat16(v);
    g_wgih[idx] = h;
    g_wgil[idx] = __float2bfloat16(v - __bfloat162float(h));

    v = wpi[k*256 + n];
    h = __float2bfloat16(v);
    g_wpih[idx] = h;
    g_wpil[idx] = __float2bfloat16(v - __bfloat162float(h));

    if (n < 128) {
        v = wgo[k*128 + n];
        h = __float2bfloat16(v);
        g_wgoh[idx] = h;
        g_wgol[idx] = __float2bfloat16(v - __bfloat162float(h));

        v = wpo[k*128 + n];   // B = wpo^T : [co=n][h=k]
        h = __float2bfloat16(v);
        g_wpoh[idx] = h;
        g_wpol[idx] = __float2bfloat16(v - __bfloat162float(h));
    }
}

// ---------------------------------------------------------------------------
// Kernel 1: proj_all — LN(x) + all three projections via split-bf16 HMMA.
// grid (4608, 3): job0 = a channels, job1 = b channels, job2 = out-gate.
// CTA: 128 tokens x 128 channels; K=128 single shot; 8 warps (2m x 4n).
// ---------------------------------------------------------------------------
#define PROW  272                 // bytes per smem row (128 bf16 + 8 pad)
#define PTILE (128*PROW)          // 34816

__global__ void __launch_bounds__(256) proj_all_kernel(
    const float* __restrict__ x, const float* __restrict__ mask,
    const float* __restrict__ nw, const float* __restrict__ nb)
{
    extern __shared__ char sm[];
    const uint32_t base  = smem_u32(sm);
    const uint32_t aHi   = base;
    const uint32_t aLo   = base + PTILE;
    const uint32_t bBase = base + 2*PTILE;

    const int tid = threadIdx.x;
    const int t0  = blockIdx.x * 128;
    const int job = blockIdx.y;

    // --- B tiles via cp.async (prepped split weights) ---
    const __nv_bfloat16* bsrc[4];
    int ntiles;
    if (job < 2) {
        bsrc[0] = g_wgih + job*128*128; bsrc[1] = g_wgil + job*128*128;
        bsrc[2] = g_wpih + job*128*128; bsrc[3] = g_wpil + job*128*128;
        ntiles = 4;
    } else {
        bsrc[0] = g_wgoh; bsrc[1] = g_wgol;
        ntiles = 2;
    }
    for (int tile = 0; tile < ntiles; tile++) {
        #pragma unroll
        for (int rep = 0; rep < 8; rep++) {
            int it  = tid + rep*256;          // 0..2047
            int row = it >> 4, q = it & 15;
            CP_ASYNC16(bBase + tile*PTILE + row*PROW + q*16,
                       (const char*)(bsrc[tile] + row*128) + q*16);
        }
    }
    CP_COMMIT();

    // --- LN(x) in registers: 2 threads per token ---
    {
        const int tl = tid >> 1, half = tid & 1;
        const float* xrow = x + (size_t)(t0 + tl)*CCH + half*64;
        float v[64];
        float s = 0.f;
        #pragma unroll
        for (int i = 0; i < 16; i++) {
            float4 f = *(const float4*)(xrow + i*4);
            v[i*4]=f.x; v[i*4+1]=f.y; v[i*4+2]=f.z; v[i*4+3]=f.w;
            s += f.x + f.y + f.z + f.w;
        }
        s += __shfl_xor_sync(0xFFFFFFFFu, s, 1);
        float m = s * (1.f/128.f);
        float q2 = 0.f;
        #pragma unroll
        for (int i = 0; i < 64; i++) { float d = v[i]-m; q2 += d*d; }
        q2 += __shfl_xor_sync(0xFFFFFFFFu, q2, 1);
        float rs = rsqrtf(q2 * (1.f/128.f) + 1e-5f);

        #pragma unroll
        for (int i = 0; i < 32; i++) {
            int k = half*64 + i*2;
            float v0 = (v[i*2]   - m)*rs*__ldg(&nw[k])   + __ldg(&nb[k]);
            float v1 = (v[i*2+1] - m)*rs*__ldg(&nw[k+1]) + __ldg(&nb[k+1]);
            __nv_bfloat16 h0 = __float2bfloat16(v0);
            __nv_bfloat16 h1 = __float2bfloat16(v1);
            __nv_bfloat162 hh; hh.x = h0; hh.y = h1;
            __nv_bfloat162 ll;
            ll.x = __float2bfloat16(v0 - __bfloat162float(h0));
            ll.y = __float2bfloat16(v1 - __bfloat162float(h1));
            *(__nv_bfloat162*)(sm + tl*PROW + k*2)         = hh;
            *(__nv_bfloat162*)(sm + PTILE + tl*PROW + k*2) = ll;
        }
    }
    CP_WAIT0();
    __syncthreads();

    // --- MMA ---
    const int wid  = tid >> 5;
    const int lane = tid & 31;
    const int m_base = (wid >> 2) * 64;
    const int n_base = (wid & 3) * 32;
    const int a_row  = lane & 15;
    const int a_half = lane >> 4;
    const int b_quad = lane >> 3;
    const int b_row  = (b_quad >> 1)*8 + (lane & 7);
    const int b_half = b_quad & 1;

    const int er = m_base + (lane >> 2);
    const int ec = n_base + (lane & 3)*2;

    if (job < 2) {
        float accg[4][4][4], accp[4][4][4];
        #pragma unroll
        for (int mt = 0; mt < 4; mt++)
            #pragma unroll
            for (int nt = 0; nt < 4; nt++)
                #pragma unroll
                for (int r = 0; r < 4; r++) { accg[mt][nt][r]=0.f; accp[mt][nt][r]=0.f; }

        #pragma unroll
        for (int ks = 0; ks < 8; ks++) {
            const uint32_t koff = ks*32;
            uint32_t Ah[4][4], Al[4][4];
            #pragma unroll
            for (int mt = 0; mt < 4; mt++) {
                uint32_t r = (m_base + mt*16 + a_row)*PROW + koff + a_half*16;
                ldsm4(Ah[mt], aHi + r);
                ldsm4(Al[mt], aLo + r);
            }
            // gate matrix (tiles 0,1) -> accg
            {
                uint32_t Bh[4][2], Bl[4][2];
                #pragma unroll
                for (int p = 0; p < 2; p++) {
                    uint32_t r = (n_base + p*16 + b_row)*PROW + koff + b_half*16;
                    uint32_t th[4], tl4[4];
                    ldsm4(th,  bBase + 0*PTILE + r);
                    ldsm4(tl4, bBase + 1*PTILE + r);
                    Bh[2*p][0]=th[0];  Bh[2*p][1]=th[1];  Bh[2*p+1][0]=th[2];  Bh[2*p+1][1]=th[3];
                    Bl[2*p][0]=tl4[0]; Bl[2*p][1]=tl4[1]; Bl[2*p+1][0]=tl4[2]; Bl[2*p+1][1]=tl4[3];
                }
                #pragma unroll
                for (int mt = 0; mt < 4; mt++)
                    #pragma unroll
                    for (int nt = 0; nt < 4; nt++) mma16816(accg[mt][nt], Ah[mt], Bh[nt]);
                #pragma unroll
                for (int mt = 0; mt < 4; mt++)
                    #pragma unroll
                    for (int nt = 0; nt < 4; nt++) mma16816(accg[mt][nt], Ah[mt], Bl[nt]);
                #pragma unroll
                for (int mt = 0; mt < 4; mt++)
                    #pragma unroll
                    for (int nt = 0; nt < 4; nt++) mma16816(accg[mt][nt], Al[mt], Bh[nt]);
            }
            // proj matrix (tiles 2,3) -> accp
            {
                uint32_t Bh[4][2], Bl[4][2];
                #pragma unroll
                for (int p = 0; p < 2; p++) {
                    uint32_t r = (n_base + p*16 + b_row)*PROW + koff + b_half*16;
                    uint32_t th[4], tl4[4];
                    ldsm4(th,  bBase + 2*PTILE + r);
                    ldsm4(tl4, bBase + 3*PTILE + r);
                    Bh[2*p][0]=th[0];  Bh[2*p][1]=th[1];  Bh[2*p+1][0]=th[2];  Bh[2*p+1][1]=th[3];
                    Bl[2*p][0]=tl4[0]; Bl[2*p][1]=tl4[1]; Bl[2*p+1][0]=tl4[2]; Bl[2*p+1][1]=tl4[3];
                }
                #pragma unroll
                for (int mt = 0; mt < 4; mt++)
                    #pragma unroll
                    for (int nt = 0; nt < 4; nt++) mma16816(accp[mt][nt], Ah[mt], Bh[nt]);
                #pragma unroll
                for (int mt = 0; mt < 4; mt++)
                    #pragma unroll
                    for (int nt = 0; nt < 4; nt++) mma16816(accp[mt][nt], Ah[mt], Bl[nt]);
                #pragma unroll
                for (int mt = 0; mt < 4; mt++)
                    #pragma unroll
                    for (int nt = 0; nt < 4; nt++) mma16816(accp[mt][nt], Al[mt], Bh[nt]);
            }
        }

        __nv_bfloat16* dHi = (job == 0) ? g_ahi : g_bhi;
        __nv_bfloat16* dLo = (job == 0) ? g_alo : g_blo;
        #pragma unroll
        for (int mt = 0; mt < 4; mt++) {
            #pragma unroll
            for (int rp = 0; rp < 2; rp++) {
                int t = t0 + er + mt*16 + rp*8;
                float mk = (job == 0) ? mask[t] : 1.f;
                #pragma unroll
                for (int nt = 0; nt < 4; nt++) {
                    #pragma unroll
                    for (int e = 0; e < 2; e++) {
                        int c = ec + nt*8 + e;
                        float g  = accg[mt][nt][rp*2+e];
                        float pv = accp[mt][nt][rp*2+e];
                        float val = sigmoidf_(g) * pv * mk;
                        __nv_bfloat16 h = __float2bfloat16(val);
                        dHi[(size_t)c*NTOK + t] = h;
                        dLo[(size_t)c*NTOK + t] = __float2bfloat16(val - __bfloat162float(h));
                    }
                }
            }
        }
    } else {
        float acc[4][4][4];
        #pragma unroll
        for (int mt = 0; mt < 4; mt++)
            #pragma unroll
            for (int nt = 0; nt < 4; nt++)
                #pragma unroll
                for (int r = 0; r < 4; r++) acc[mt][nt][r] = 0.f;

        #pragma unroll
        for (int ks = 0; ks < 8; ks++) {
            const uint32_t koff = ks*32;
            uint32_t Ah[4][4], Al[4][4];
            #pragma unroll
            for (int mt = 0; mt < 4; mt++) {
                uint32_t r = (m_base + mt*16 + a_row)*PROW + koff + a_half*16;
                ldsm4(Ah[mt], aHi + r);
                ldsm4(Al[mt], aLo + r);
            }
            uint32_t Bh[4][2], Bl[4][2];
            #pragma unroll
            for (int p = 0; p < 2; p++) {
                uint32_t r = (n_base + p*16 + b_row)*PROW + koff + b_half*16;
                uint32_t th[4], tl4[4];
                ldsm4(th,  bBase + 0*PTILE + r);
                ldsm4(tl4, bBase + 1*PTILE + r);
                Bh[2*p][0]=th[0];  Bh[2*p][1]=th[1];  Bh[2*p+1][0]=th[2];  Bh[2*p+1][1]=th[3];
                Bl[2*p][0]=tl4[0]; Bl[2*p][1]=tl4[1]; Bl[2*p+1][0]=tl4[2]; Bl[2*p+1][1]=tl4[3];
            }
            #pragma unroll
            for (int mt = 0; mt < 4; mt++)
                #pragma unroll
                for (int nt = 0; nt < 4; nt++) mma16816(acc[mt][nt], Ah[mt], Bh[nt]);
            #pragma unroll
            for (int mt = 0; mt < 4; mt++)
                #pragma unroll
                for (int nt = 0; nt < 4; nt++) mma16816(acc[mt][nt], Ah[mt], Bl[nt]);
            #pragma unroll
            for (int mt = 0; mt < 4; mt++)
                #pragma unroll
                for (int nt = 0; nt < 4; nt++) mma16816(acc[mt][nt], Al[mt], Bh[nt]);
        }

        #pragma unroll
        for (int mt = 0; mt < 4; mt++) {
            #pragma unroll
            for (int rp = 0; rp < 2; rp++) {
                int t = t0 + er + mt*16 + rp*8;
                #pragma unroll
                for (int nt = 0; nt < 4; nt++) {
                    int c = ec + nt*8;
                    float2 f = make_float2(sigmoidf_(acc[mt][nt][rp*2]),
                                           sigmoidf_(acc[mt][nt][rp*2+1]));
                    *(float2*)&g_gate[(size_t)t*CCH + c] = f;
                }
            }
        }
    }
}

// ---------------------------------------------------------------------------
// Kernel 2: triangle einsum via mma.sync bf16 split (3 passes). (unchanged)
// ---------------------------------------------------------------------------
#define ROWB   144
#define TILEB  (128*ROWB)
#define CHUNKB (4*TILEB)

__device__ __forceinline__ void tri_load_chunk(
    uint32_t sbuf, const __nv_bfloat16* s0, const __nv_bfloat16* s1,
    const __nv_bfloat16* s2, const __nv_bfloat16* s3, int kk, int tid)
{
    const __nv_bfloat16* srcs[4] = {s0, s1, s2, s3};
    #pragma unroll
    for (int rep = 0; rep < 16; rep++) {
        int it   = tid + rep*256;
        int tile = it >> 10;
        int row  = (it >> 3) & 127;
        int q8   = it & 7;
        const __nv_bfloat16* gp = srcs[tile] + (size_t)row*SDIM + kk + q8*8;
        CP_ASYNC16(sbuf + tile*TILEB + row*ROWB + q8*16, gp);
    }
}

__global__ void __launch_bounds__(256) tri_mma_kernel()
{
    extern __shared__ char dynsm[];
    const uint32_t base = smem_u32(dynsm);

    const int tid  = threadIdx.x;
    const int wid  = tid >> 5;
    const int lane = tid & 31;
    const int m_base = (wid >> 2) * 64;
    const int n_base = (wid & 3) * 32;

    const int c  = blockIdx.y;
    const int i0 = (blockIdx.x / 6) * 128;
    const int j0 = (blockIdx.x % 6) * 128;

    const __nv_bfloat16* sAh = g_ahi + (size_t)c*NTOK + (size_t)i0*SDIM;
    const __nv_bfloat16* sAl = g_alo + (size_t)c*NTOK + (size_t)i0*SDIM;
    const __nv_bfloat16* sBh = g_bhi + (size_t)c*NTOK + (size_t)j0*SDIM;
    const __nv_bfloat16* sBl = g_blo + (size_t)c*NTOK + (size_t)j0*SDIM;

    float acc[4][4][4];
    #pragma unroll
    for (int mt = 0; mt < 4; mt++)
        #pragma unroll
        for (int nt = 0; nt < 4; nt++)
            #pragma unroll
            for (int r = 0; r < 4; r++) acc[mt][nt][r] = 0.f;

    const int a_row  = lane & 15;
    const int a_half = lane >> 4;
    const int b_quad = lane >> 3;
    const int b_row  = (b_quad >> 1) * 8 + (lane & 7);
    const int b_half = b_quad & 1;

    tri_load_chunk(base, sAh, sAl, sBh, sBl, 0, tid);
    CP_COMMIT();

    for (int n = 0; n < 12; n++) {
        if (n < 11) {
            tri_load_chunk(base + ((n+1)&1)*CHUNKB, sAh, sAl, sBh, sBl, (n+1)*64, tid);
            CP_COMMIT();
            CP_WAIT1();
        } else {
            CP_WAIT0();
        }
        __syncthreads();

        const uint32_t sb = base + (n&1)*CHUNKB;
        #pragma unroll
        for (int ks = 0; ks < 4; ks++) {
            uint32_t Ah[4][4], Al[4][4], Bh[4][2], Bl[4][2];
            const uint32_t koff = ks*32;
            #pragma unroll
            for (int mt = 0; mt < 4; mt++) {
                uint32_t r = (m_base + mt*16 + a_row)*ROWB + koff + a_half*16;
                ldsm4(Ah[mt], sb + 0*TILEB + r);
                ldsm4(Al[mt], sb + 1*TILEB + r);
            }
            #pragma unroll
            for (int p = 0; p < 2; p++) {
                uint32_t r = (n_base + p*16 + b_row)*ROWB + koff + b_half*16;
                uint32_t th[4], tl[4];
                ldsm4(th, sb + 2*TILEB + r);
                ldsm4(tl, sb + 3*TILEB + r);
                Bh[2*p][0]   = th[0]; Bh[2*p][1]   = th[1];
                Bh[2*p+1][0] = th[2]; Bh[2*p+1][1] = th[3];
                Bl[2*p][0]   = tl[0]; Bl[2*p][1]   = tl[1];
                Bl[2*p+1][0] = tl[2]; Bl[2*p+1][1] = tl[3];
            }
            #pragma unroll
            for (int mt = 0; mt < 4; mt++)
                #pragma unroll
                for (int nt = 0; nt < 4; nt++)
                    mma16816(acc[mt][nt], Ah[mt], Bh[nt]);
            #pragma unroll
            for (int mt = 0; mt < 4; mt++)
                #pragma unroll
                for (int nt = 0; nt < 4; nt++)
                    mma16816(acc[mt][nt], Ah[mt], Bl[nt]);
            #pragma unroll
            for (int mt = 0; mt < 4; mt++)
                #pragma unroll
                for (int nt = 0; nt < 4; nt++)
                    mma16816(acc[mt][nt], Al[mt], Bh[nt]);
        }
        __syncthreads();
    }

    float* T = g_tri + (size_t)c*NTOK;
    const int er = i0 + m_base + (lane >> 2);
    const int ec = j0 + n_base + (lane & 3)*2;
    #pragma unroll
    for (int mt = 0; mt < 4; mt++) {
        #pragma unroll
        for (int nt = 0; nt < 4; nt++) {
            int rr = er + mt*16;
            int cc = ec + nt*8;
            *(float2*)&T[(size_t)rr*SDIM + cc]     = make_float2(acc[mt][nt][0], acc[mt][nt][1]);
            *(float2*)&T[(size_t)(rr+8)*SDIM + cc] = make_float2(acc[mt][nt][2], acc[mt][nt][3]);
        }
    }
}

// ---------------------------------------------------------------------------
// Kernel 3: out = LN(tri) @ w_p_out * gate, via split-bf16 HMMA.
// grid 4608, CTA: 128 tokens x 128 cout, K=128.
// ---------------------------------------------------------------------------
#define OUT_TRIS   (128*528)              // tri f32 staging, rows 132 f32
#define OUT_AHI    OUT_TRIS               // 67584
#define OUT_ALO    (OUT_AHI + PTILE)
#define OUT_B      (OUT_ALO + PTILE)
#define OUT_SMEM   (OUT_B + 2*PTILE)      // 206848

__global__ void __launch_bounds__(256) out_mma_kernel(
    const float* __restrict__ now, const float* __restrict__ nob,
    float* __restrict__ out)
{
    extern __shared__ char sm[];
    const uint32_t base = smem_u32(sm);
    const int tid = threadIdx.x;
    const int t0  = blockIdx.x * 128;

    // B tiles (w_p_out^T split)
    const __nv_bfloat16* bsrc[2] = { g_wpoh, g_wpol };
    for (int tile = 0; tile < 2; tile++) {
        #pragma unroll
        for (int rep = 0; rep < 8; rep++) {
            int it = tid + rep*256;
            int row = it >> 4, q = it & 15;
            CP_ASYNC16(base + OUT_B + tile*PTILE + row*PROW + q*16,
                       (const char*)(bsrc[tile] + row*128) + q*16);
        }
    }
    // tri tile staging [ch][t] (rows 528B)
    #pragma unroll
    for (int rep = 0; rep < 16; rep++) {
        int it = tid + rep*256;          // 0..4095
        int row = it >> 5, q = it & 31;
        CP_ASYNC16(base + row*528 + q*16,
                   g_tri + (size_t)row*NTOK + t0 + q*4);
    }
    CP_COMMIT();
    CP_WAIT0();
    __syncthreads();

    // LN over channels, write split-bf16 A [t][ch]
    {
        float* trs = (float*)sm;
        const int tl = tid >> 1, half = tid & 1;
        float s = 0.f;
        #pragma unroll 8
        for (int j = 0; j < 64; j++) s += trs[(half*64 + j)*132 + tl];
        s += __shfl_xor_sync(0xFFFFFFFFu, s, 1);
        float m = s * (1.f/128.f);
        float q2 = 0.f;
        #pragma unroll 8
        for (int j = 0; j < 64; j++) {
            float d = trs[(half*64 + j)*132 + tl] - m;
            q2 += d*d;
        }
        q2 += __shfl_xor_sync(0xFFFFFFFFu, q2, 1);
        float rs = rsqrtf(q2 * (1.f/128.f) + 1e-5f);

        #pragma unroll
        for (int j = 0; j < 32; j++) {
            int ch = half*64 + j*2;
            float v0 = (trs[ch*132 + tl]     - m)*rs*__ldg(&now[ch])   + __ldg(&nob[ch]);
            float v1 = (trs[(ch+1)*132 + tl] - m)*rs*__ldg(&now[ch+1]) + __ldg(&nob[ch+1]);
            __nv_bfloat16 h0 = __float2bfloat16(v0);
            __nv_bfloat16 h1 = __float2bfloat16(v1);
            __nv_bfloat162 hh; hh.x = h0; hh.y = h1;
            __nv_bfloat162 ll;
            ll.x = __float2bfloat16(v0 - __bfloat162float(h0));
            ll.y = __float2bfloat16(v1 - __bfloat162float(h1));
            *(__nv_bfloat162*)(sm + OUT_AHI + tl*PROW + ch*2) = hh;
            *(__nv_bfloat162*)(sm + OUT_ALO + tl*PROW + ch*2) = ll;
        }
    }
    __syncthreads();

    // MMA
    const int wid  = tid >> 5;
    const int lane = tid & 31;
    const int m_base = (wid >> 2) * 64;
    const int n_base = (wid & 3) * 32;
    const int a_row  = lane & 15;
    const int a_half = lane >> 4;
    const int b_quad = lane >> 3;
    const int b_row  = (b_quad >> 1)*8 + (lane & 7);
    const int b_half = b_quad & 1;

    float acc[4][4][4];
    #pragma unroll
    for (int mt = 0; mt < 4; mt++)
        #pragma unroll
        for (int nt = 0; nt < 4; nt++)
            #pragma unroll
            for (int r = 0; r < 4; r++) acc[mt][nt][r] = 0.f;

    #pragma unroll
    for (int ks = 0; ks < 8; ks++) {
        const uint32_t koff = ks*32;
        uint32_t Ah[4][4], Al[4][4];
        #pragma unroll
        for (int mt = 0; mt < 4; mt++) {
            uint32_t r = (m_base + mt*16 + a_row)*PROW + koff + a_half*16;
            ldsm4(Ah[mt], base + OUT_AHI + r);
            ldsm4(Al[mt], base + OUT_ALO + r);
        }
        uint32_t Bh[4][2], Bl[4][2];
        #pragma unroll
        for (int p = 0; p < 2; p++) {
            uint32_t r = (n_base + p*16 + b_row)*PROW + koff + b_half*16;
            uint32_t th[4], tl4[4];
            ldsm4(th,  base + OUT_B + 0*PTILE + r);
            ldsm4(tl4, base + OUT_B + 1*PTILE + r);
            Bh[2*p][0]=th[0];  Bh[2*p][1]=th[1];  Bh[2*p+1][0]=th[2];  Bh[2*p+1][1]=th[3];
            Bl[2*p][0]=tl4[0]; Bl[2*p][1]=tl4[1]; Bl[2*p+1][0]=tl4[2]; Bl[2*p+1][1]=tl4[3];
        }
        #pragma unroll
        for (int mt = 0; mt < 4; mt++)
            #pragma unroll
            for (int nt = 0; nt < 4; nt++) mma16816(acc[mt][nt], Ah[mt], Bh[nt]);
        #pragma unroll
        for (int mt = 0; mt < 4; mt++)
            #pragma unroll
            for (int nt = 0; nt < 4; nt++) mma16816(acc[mt][nt], Ah[mt], Bl[nt]);
        #pragma unroll
        for (int mt = 0; mt < 4; mt++)
            #pragma unroll
            for (int nt = 0; nt < 4; nt++) mma16816(acc[mt][nt], Al[mt], Bh[nt]);
    }

    const int er = m_base + (lane >> 2);
    const int ec = n_base + (lane & 3)*2;
    #pragma unroll
    for (int mt = 0; mt < 4; mt++) {
        #pragma unroll
        for (int rp = 0; rp < 2; rp++) {
            int t = t0 + er + mt*16 + rp*8;
            #pragma unroll
            for (int nt = 0; nt < 4; nt++) {
                int cc = ec + nt*8;
                float2 gg = *(const float2*)&g_gate[(size_t)t*CCH + cc];
                float2 o = make_float2(acc[mt][nt][rp*2]   * gg.x,
                                       acc[mt][nt][rp*2+1] * gg.y);
                *(float2*)&out[(size_t)t*CCH + cc] = o;
            }
        }
    }
}

// ---------------------------------------------------------------------------
extern "C" void kernel_launch(void* const* d_in, const int* in_sizes, int n_in,
                              void* d_out, int out_size)
{
    const float* x    = (const float*)d_in[0];
    const float* mask = (const float*)d_in[1];
    const float* niw  = (const float*)d_in[2];
    const float* nib  = (const float*)d_in[3];
    const float* wgi  = (const float*)d_in[4];
    const float* wpi  = (const float*)d_in[5];
    const float* now  = (const float*)d_in[6];
    const float* nob  = (const float*)d_in[7];
    const float* wgo  = (const float*)d_in[8];
    const float* wpo  = (const float*)d_in[9];
    float* out = (float*)d_out;

    const int smem_proj = 6*PTILE;       // 208896
    const int smem_tri  = 2*CHUNKB;      // 147456
    const int smem_out  = OUT_SMEM;      // 206848
    cudaFuncSetAttribute(proj_all_kernel,
        cudaFuncAttributeMaxDynamicSharedMemorySize, smem_proj);
    cudaFuncSetAttribute(tri_mma_kernel,
        cudaFuncAttributeMaxDynamicSharedMemorySize, smem_tri);
    cudaFuncSetAttribute(out_mma_kernel,
        cudaFuncAttributeMaxDynamicSharedMemorySize, smem_out);

    prep_w_kernel<<<128, 256>>>(wgi, wpi, wgo, wpo);
    proj_all_kernel<<<dim3(NTOK/128, 3), 256, smem_proj>>>(x, mask, niw, nib);
    tri_mma_kernel<<<dim3(36, 128), 256, smem_tri>>>();
    out_mma_kernel<<<NTOK/128, 256, smem_out>>>(now, nob, out);
}

// round 5
// speedup vs baseline: 2.6012x; 1.0770x over previous
#include <cuda_runtime.h>
#include <cuda_bf16.h>
#include <math.h>
#include <stdint.h>

#define SDIM 768
#define CCH  128
#define NTOK (SDIM*SDIM)        // 589824 tokens
#define SELEM 75497472          // 128 * 589824
#define NSM   148

// Scratch
__device__ __nv_bfloat16 g_ahi[SELEM];
__device__ __nv_bfloat16 g_alo[SELEM];
__device__ __nv_bfloat16 g_bhi[SELEM];
__device__ __nv_bfloat16 g_blo[SELEM];
__device__ float g_tri[SELEM];
__device__ float g_gate[SELEM];

// Prepped split-bf16 weights, [n][k] layout (k contiguous, 128 per row)
__device__ __nv_bfloat16 g_wgih[256*128], g_wgil[256*128];
__device__ __nv_bfloat16 g_wpih[256*128], g_wpil[256*128];
__device__ __nv_bfloat16 g_wgoh[128*128], g_wgol[128*128];
__device__ __nv_bfloat16 g_wpoh[128*128], g_wpol[128*128];

__device__ __forceinline__ float sigmoidf_(float v) {
    return 1.f / (1.f + __expf(-v));
}
__device__ __forceinline__ uint32_t smem_u32(const void* p) {
    uint32_t a;
    asm("{ .reg .u64 t; cvta.to.shared.u64 t, %1; cvt.u32.u64 %0, t; }"
        : "=r"(a) : "l"(p));
    return a;
}
#define CP_ASYNC16(d, s)  asm volatile("cp.async.cg.shared.global [%0], [%1], 16;" :: "r"(d), "l"(s))
#define CP_COMMIT()       asm volatile("cp.async.commit_group;" ::: "memory")
#define CP_WAIT0()        asm volatile("cp.async.wait_group 0;" ::: "memory")
#define CP_WAIT1()        asm volatile("cp.async.wait_group 1;" ::: "memory")

__device__ __forceinline__ void ldsm4(uint32_t* r, uint32_t addr) {
    asm volatile("ldmatrix.sync.aligned.m8n8.x4.shared.b16 {%0,%1,%2,%3}, [%4];"
        : "=r"(r[0]), "=r"(r[1]), "=r"(r[2]), "=r"(r[3]) : "r"(addr));
}
__device__ __forceinline__ void mma16816(float* d, const uint32_t* a, const uint32_t* b) {
    asm volatile("mma.sync.aligned.m16n8k16.row.col.f32.bf16.bf16.f32 "
        "{%0,%1,%2,%3}, {%4,%5,%6,%7}, {%8,%9}, {%0,%1,%2,%3};"
        : "+f"(d[0]), "+f"(d[1]), "+f"(d[2]), "+f"(d[3])
        : "r"(a[0]), "r"(a[1]), "r"(a[2]), "r"(a[3]), "r"(b[0]), "r"(b[1]));
}
__device__ __forceinline__ uint32_t pack_split(float v) {
    __nv_bfloat16 h = __float2bfloat16(v);
    __nv_bfloat16 l = __float2bfloat16(v - __bfloat162float(h));
    return (uint32_t)__bfloat16_as_ushort(h) | ((uint32_t)__bfloat16_as_ushort(l) << 16);
}

// ---------------------------------------------------------------------------
// Kernel 0: weight prep — transpose + split to bf16 hi/lo, [n][k].
// ---------------------------------------------------------------------------
__global__ void __launch_bounds__(256) prep_w_kernel(
    const float* __restrict__ wgi, const float* __restrict__ wpi,
    const float* __restrict__ wgo, const float* __restrict__ wpo)
{
    int idx = blockIdx.x*256 + threadIdx.x;   // 0..32767
    int n = idx >> 7, k = idx & 127;

    float v = wgi[k*256 + n];
    __nv_bfloat16 h = __float2bfloat16(v);
    g_wgih[idx] = h;
    g_wgil[idx] = __float2bfloat16(v - __bfloat162float(h));

    v = wpi[k*256 + n];
    h = __float2bfloat16(v);
    g_wpih[idx] = h;
    g_wpil[idx] = __float2bfloat16(v - __bfloat162float(h));

    if (n < 128) {
        v = wgo[k*128 + n];
        h = __float2bfloat16(v);
        g_wgoh[idx] = h;
        g_wgol[idx] = __float2bfloat16(v - __bfloat162float(h));

        v = wpo[k*128 + n];   // B = wpo^T : [co=n][h=k]
        h = __float2bfloat16(v);
        g_wpoh[idx] = h;
        g_wpol[idx] = __float2bfloat16(v - __bfloat162float(h));
    }
}

// ---------------------------------------------------------------------------
// Kernel 1: proj_persist — persistent; LN(x) + projections via split HMMA.
// grid (148, 3): job0 = a channels, job1 = b channels, job2 = out-gate.
// Tile: 64 tokens x 128 out-channels, K=128. Prefetch next x tile during MMA.
// ---------------------------------------------------------------------------
#define PROW   272                // bytes per A/B smem row (128 bf16 + pad)
#define PTILE  (128*PROW)         // 34816 (B tile / 128-row A tile)
#define ATILE  (64*PROW)          // 17408 (64-row A tile)
#define XROW   528                // x / tri staging row: 128 f32 + pad
// proj smem layout
#define PJ_AHI   0
#define PJ_ALO   ATILE
#define PJ_B     (2*ATILE)                 // 34816
#define PJ_STG   (PJ_B + 4*PTILE)          // 174080
#define PJ_SMEM  (PJ_STG + 64*XROW)        // 207872
#define NPTILE   (NTOK/64)                 // 9216

__global__ void __launch_bounds__(256) proj_persist_kernel(
    const float* __restrict__ x, const float* __restrict__ mask,
    const float* __restrict__ nw, const float* __restrict__ nb)
{
    extern __shared__ char sm[];
    const uint32_t base = smem_u32(sm);
    const int tid = threadIdx.x;
    const int bid = blockIdx.x;
    const int job = blockIdx.y;

    // --- one-time B tiles ---
    const __nv_bfloat16* bsrc[4];
    int ntiles;
    if (job < 2) {
        bsrc[0] = g_wgih + job*128*128; bsrc[1] = g_wgil + job*128*128;
        bsrc[2] = g_wpih + job*128*128; bsrc[3] = g_wpil + job*128*128;
        ntiles = 4;
    } else {
        bsrc[0] = g_wgoh; bsrc[1] = g_wgol;
        ntiles = 2;
    }
    for (int tile = 0; tile < ntiles; tile++) {
        #pragma unroll
        for (int rep = 0; rep < 8; rep++) {
            int it  = tid + rep*256;
            int row = it >> 4, q = it & 15;
            CP_ASYNC16(base + PJ_B + tile*PTILE + row*PROW + q*16,
                       (const char*)(bsrc[tile] + row*128) + q*16);
        }
    }
    // first x tile
    {
        int t0 = bid * 64;
        #pragma unroll
        for (int rep = 0; rep < 8; rep++) {
            int it = tid + rep*256;
            int row = it >> 5, q = it & 31;
            CP_ASYNC16(base + PJ_STG + row*XROW + q*16,
                       x + (size_t)(t0 + row)*CCH + q*4);
        }
    }
    CP_COMMIT();

    // thread mapping
    const int wid  = tid >> 5;
    const int lane = tid & 31;
    const int m_base = (wid >> 2) * 32;   // 2 m-warps, warp M=32
    const int n_base = (wid & 3) * 32;    // 4 n-warps, warp N=32
    const int a_row  = lane & 15;
    const int a_half = lane >> 4;
    const int b_quad = lane >> 3;
    const int b_row  = (b_quad >> 1)*8 + (lane & 7);
    const int b_half = b_quad & 1;
    const int er = m_base + (lane >> 2);
    const int ec = n_base + (lane & 3)*2;

    const float* xstg = (const float*)(sm + PJ_STG);
    const int tl = tid >> 2, qq = tid & 3;     // LN: 4 threads per token

    for (int tile = bid; tile < NPTILE; tile += NSM) {
        const int t0 = tile * 64;
        CP_WAIT0();
        __syncthreads();

        // --- LN from staging -> split A (smem) ---
        {
            float v[32];
            float s = 0.f;
            #pragma unroll
            for (int i = 0; i < 8; i++) {
                float4 f = *(const float4*)&xstg[tl*132 + qq*32 + i*4];
                v[i*4]=f.x; v[i*4+1]=f.y; v[i*4+2]=f.z; v[i*4+3]=f.w;
                s += f.x + f.y + f.z + f.w;
            }
            s += __shfl_xor_sync(0xFFFFFFFFu, s, 1);
            s += __shfl_xor_sync(0xFFFFFFFFu, s, 2);
            float m = s * (1.f/128.f);
            float q2 = 0.f;
            #pragma unroll
            for (int i = 0; i < 32; i++) { float d = v[i]-m; q2 += d*d; }
            q2 += __shfl_xor_sync(0xFFFFFFFFu, q2, 1);
            q2 += __shfl_xor_sync(0xFFFFFFFFu, q2, 2);
            float rs = rsqrtf(q2 * (1.f/128.f) + 1e-5f);

            #pragma unroll
            for (int i = 0; i < 16; i++) {
                int k = qq*32 + i*2;
                float v0 = (v[i*2]   - m)*rs*__ldg(&nw[k])   + __ldg(&nb[k]);
                float v1 = (v[i*2+1] - m)*rs*__ldg(&nw[k+1]) + __ldg(&nb[k+1]);
                __nv_bfloat16 h0 = __float2bfloat16(v0);
                __nv_bfloat16 h1 = __float2bfloat16(v1);
                __nv_bfloat162 hh; hh.x = h0; hh.y = h1;
                __nv_bfloat162 ll;
                ll.x = __float2bfloat16(v0 - __bfloat162float(h0));
                ll.y = __float2bfloat16(v1 - __bfloat162float(h1));
                *(__nv_bfloat162*)(sm + PJ_AHI + tl*PROW + k*2) = hh;
                *(__nv_bfloat162*)(sm + PJ_ALO + tl*PROW + k*2) = ll;
            }
        }
        __syncthreads();

        // --- prefetch next x tile (overlaps MMA) ---
        if (tile + NSM < NPTILE) {
            int nt0 = (tile + NSM) * 64;
            #pragma unroll
            for (int rep = 0; rep < 8; rep++) {
                int it = tid + rep*256;
                int row = it >> 5, q = it & 31;
                CP_ASYNC16(base + PJ_STG + row*XROW + q*16,
                           x + (size_t)(nt0 + row)*CCH + q*4);
            }
        }
        CP_COMMIT();

        if (job < 2) {
            float accg[2][4][4], accp[2][4][4];
            #pragma unroll
            for (int mt = 0; mt < 2; mt++)
                #pragma unroll
                for (int nt = 0; nt < 4; nt++)
                    #pragma unroll
                    for (int r = 0; r < 4; r++) { accg[mt][nt][r]=0.f; accp[mt][nt][r]=0.f; }

            #pragma unroll
            for (int ks = 0; ks < 8; ks++) {
                const uint32_t koff = ks*32;
                uint32_t Ah[2][4], Al[2][4];
                #pragma unroll
                for (int mt = 0; mt < 2; mt++) {
                    uint32_t r = (m_base + mt*16 + a_row)*PROW + koff + a_half*16;
                    ldsm4(Ah[mt], base + PJ_AHI + r);
                    ldsm4(Al[mt], base + PJ_ALO + r);
                }
                #pragma unroll
                for (int g = 0; g < 2; g++) {      // g=0: gate, g=1: proj
                    uint32_t Bh[4][2], Bl[4][2];
                    #pragma unroll
                    for (int p = 0; p < 2; p++) {
                        uint32_t r = (n_base + p*16 + b_row)*PROW + koff + b_half*16;
                        uint32_t th[4], tl4[4];
                        ldsm4(th,  base + PJ_B + (2*g+0)*PTILE + r);
                        ldsm4(tl4, base + PJ_B + (2*g+1)*PTILE + r);
                        Bh[2*p][0]=th[0];  Bh[2*p][1]=th[1];  Bh[2*p+1][0]=th[2];  Bh[2*p+1][1]=th[3];
                        Bl[2*p][0]=tl4[0]; Bl[2*p][1]=tl4[1]; Bl[2*p+1][0]=tl4[2]; Bl[2*p+1][1]=tl4[3];
                    }
                    float (*acc)[4][4] = g ? accp : accg;
                    #pragma unroll
                    for (int mt = 0; mt < 2; mt++)
                        #pragma unroll
                        for (int nt = 0; nt < 4; nt++) mma16816(acc[mt][nt], Ah[mt], Bh[nt]);
                    #pragma unroll
                    for (int mt = 0; mt < 2; mt++)
                        #pragma unroll
                        for (int nt = 0; nt < 4; nt++) mma16816(acc[mt][nt], Ah[mt], Bl[nt]);
                    #pragma unroll
                    for (int mt = 0; mt < 2; mt++)
                        #pragma unroll
                        for (int nt = 0; nt < 4; nt++) mma16816(acc[mt][nt], Al[mt], Bh[nt]);
                }
            }
            __syncthreads();   // all warps done reading A; reuse A region

            // transpose via smem: u32(hi,lo) at [c][t], row stride 68 u32
            uint32_t* tp = (uint32_t*)(sm + PJ_AHI);
            #pragma unroll
            for (int mt = 0; mt < 2; mt++) {
                #pragma unroll
                for (int rp = 0; rp < 2; rp++) {
                    int t_loc = m_base + mt*16 + rp*8 + (lane >> 2);
                    float mk = (job == 0) ? __ldg(&mask[t0 + t_loc]) : 1.f;
                    #pragma unroll
                    for (int nt = 0; nt < 4; nt++) {
                        #pragma unroll
                        for (int e = 0; e < 2; e++) {
                            int c = ec + nt*8 + e;
                            float val = sigmoidf_(accg[mt][nt][rp*2+e]) * accp[mt][nt][rp*2+e] * mk;
                            tp[c*68 + t_loc] = pack_split(val);
                        }
                    }
                }
            }
            __syncthreads();

            // coalesced stores: per c row, bf16x2 pairs
            uint32_t* dHi = (uint32_t*)((job == 0) ? g_ahi : g_bhi);
            uint32_t* dLo = (uint32_t*)((job == 0) ? g_alo : g_blo);
            #pragma unroll
            for (int rep = 0; rep < 16; rep++) {
                int idx = tid + rep*256;          // 0..4095
                int c = idx >> 5, t2 = idx & 31;
                uint32_t u0 = tp[c*68 + t2*2];
                uint32_t u1 = tp[c*68 + t2*2 + 1];
                uint32_t hi2 = (u0 & 0xFFFFu) | (u1 << 16);
                uint32_t lo2 = (u0 >> 16) | (u1 & 0xFFFF0000u);
                size_t o = ((size_t)c*NTOK + t0) >> 1;
                dHi[o + t2] = hi2;
                dLo[o + t2] = lo2;
            }
        } else {
            float acc[2][4][4];
            #pragma unroll
            for (int mt = 0; mt < 2; mt++)
                #pragma unroll
                for (int nt = 0; nt < 4; nt++)
                    #pragma unroll
                    for (int r = 0; r < 4; r++) acc[mt][nt][r] = 0.f;

            #pragma unroll
            for (int ks = 0; ks < 8; ks++) {
                const uint32_t koff = ks*32;
                uint32_t Ah[2][4], Al[2][4];
                #pragma unroll
                for (int mt = 0; mt < 2; mt++) {
                    uint32_t r = (m_base + mt*16 + a_row)*PROW + koff + a_half*16;
                    ldsm4(Ah[mt], base + PJ_AHI + r);
                    ldsm4(Al[mt], base + PJ_ALO + r);
                }
                uint32_t Bh[4][2], Bl[4][2];
                #pragma unroll
                for (int p = 0; p < 2; p++) {
                    uint32_t r = (n_base + p*16 + b_row)*PROW + koff + b_half*16;
                    uint32_t th[4], tl4[4];
                    ldsm4(th,  base + PJ_B + 0*PTILE + r);
                    ldsm4(tl4, base + PJ_B + 1*PTILE + r);
                    Bh[2*p][0]=th[0];  Bh[2*p][1]=th[1];  Bh[2*p+1][0]=th[2];  Bh[2*p+1][1]=th[3];
                    Bl[2*p][0]=tl4[0]; Bl[2*p][1]=tl4[1]; Bl[2*p+1][0]=tl4[2]; Bl[2*p+1][1]=tl4[3];
                }
                #pragma unroll
                for (int mt = 0; mt < 2; mt++)
                    #pragma unroll
                    for (int nt = 0; nt < 4; nt++) mma16816(acc[mt][nt], Ah[mt], Bh[nt]);
                #pragma unroll
                for (int mt = 0; mt < 2; mt++)
                    #pragma unroll
                    for (int nt = 0; nt < 4; nt++) mma16816(acc[mt][nt], Ah[mt], Bl[nt]);
                #pragma unroll
                for (int mt = 0; mt < 2; mt++)
                    #pragma unroll
                    for (int nt = 0; nt < 4; nt++) mma16816(acc[mt][nt], Al[mt], Bh[nt]);
            }

            #pragma unroll
            for (int mt = 0; mt < 2; mt++) {
                #pragma unroll
                for (int rp = 0; rp < 2; rp++) {
                    int t = t0 + m_base + mt*16 + rp*8 + (lane >> 2);
                    #pragma unroll
                    for (int nt = 0; nt < 4; nt++) {
                        int c = ec + nt*8;
                        float2 f = make_float2(sigmoidf_(acc[mt][nt][rp*2]),
                                               sigmoidf_(acc[mt][nt][rp*2+1]));
                        *(float2*)&g_gate[(size_t)t*CCH + c] = f;
                    }
                }
            }
            __syncthreads();   // keep A region stable until all warps done
        }
    }
}

// ---------------------------------------------------------------------------
// Kernel 2: triangle einsum via mma.sync bf16 split (3 passes). (unchanged)
// ---------------------------------------------------------------------------
#define ROWB   144
#define TILEB  (128*ROWB)
#define CHUNKB (4*TILEB)

__device__ __forceinline__ void tri_load_chunk(
    uint32_t sbuf, const __nv_bfloat16* s0, const __nv_bfloat16* s1,
    const __nv_bfloat16* s2, const __nv_bfloat16* s3, int kk, int tid)
{
    const __nv_bfloat16* srcs[4] = {s0, s1, s2, s3};
    #pragma unroll
    for (int rep = 0; rep < 16; rep++) {
        int it   = tid + rep*256;
        int tile = it >> 10;
        int row  = (it >> 3) & 127;
        int q8   = it & 7;
        const __nv_bfloat16* gp = srcs[tile] + (size_t)row*SDIM + kk + q8*8;
        CP_ASYNC16(sbuf + tile*TILEB + row*ROWB + q8*16, gp);
    }
}

__global__ void __launch_bounds__(256) tri_mma_kernel()
{
    extern __shared__ char dynsm[];
    const uint32_t base = smem_u32(dynsm);

    const int tid  = threadIdx.x;
    const int wid  = tid >> 5;
    const int lane = tid & 31;
    const int m_base = (wid >> 2) * 64;
    const int n_base = (wid & 3) * 32;

    const int c  = blockIdx.y;
    const int i0 = (blockIdx.x / 6) * 128;
    const int j0 = (blockIdx.x % 6) * 128;

    const __nv_bfloat16* sAh = g_ahi + (size_t)c*NTOK + (size_t)i0*SDIM;
    const __nv_bfloat16* sAl = g_alo + (size_t)c*NTOK + (size_t)i0*SDIM;
    const __nv_bfloat16* sBh = g_bhi + (size_t)c*NTOK + (size_t)j0*SDIM;
    const __nv_bfloat16* sBl = g_blo + (size_t)c*NTOK + (size_t)j0*SDIM;

    float acc[4][4][4];
    #pragma unroll
    for (int mt = 0; mt < 4; mt++)
        #pragma unroll
        for (int nt = 0; nt < 4; nt++)
            #pragma unroll
            for (int r = 0; r < 4; r++) acc[mt][nt][r] = 0.f;

    const int a_row  = lane & 15;
    const int a_half = lane >> 4;
    const int b_quad = lane >> 3;
    const int b_row  = (b_quad >> 1) * 8 + (lane & 7);
    const int b_half = b_quad & 1;

    tri_load_chunk(base, sAh, sAl, sBh, sBl, 0, tid);
    CP_COMMIT();

    for (int n = 0; n < 12; n++) {
        if (n < 11) {
            tri_load_chunk(base + ((n+1)&1)*CHUNKB, sAh, sAl, sBh, sBl, (n+1)*64, tid);
            CP_COMMIT();
            CP_WAIT1();
        } else {
            CP_WAIT0();
        }
        __syncthreads();

        const uint32_t sb = base + (n&1)*CHUNKB;
        #pragma unroll
        for (int ks = 0; ks < 4; ks++) {
            uint32_t Ah[4][4], Al[4][4], Bh[4][2], Bl[4][2];
            const uint32_t koff = ks*32;
            #pragma unroll
            for (int mt = 0; mt < 4; mt++) {
                uint32_t r = (m_base + mt*16 + a_row)*ROWB + koff + a_half*16;
                ldsm4(Ah[mt], sb + 0*TILEB + r);
                ldsm4(Al[mt], sb + 1*TILEB + r);
            }
            #pragma unroll
            for (int p = 0; p < 2; p++) {
                uint32_t r = (n_base + p*16 + b_row)*ROWB + koff + b_half*16;
                uint32_t th[4], tl[4];
                ldsm4(th, sb + 2*TILEB + r);
                ldsm4(tl, sb + 3*TILEB + r);
                Bh[2*p][0]   = th[0]; Bh[2*p][1]   = th[1];
                Bh[2*p+1][0] = th[2]; Bh[2*p+1][1] = th[3];
                Bl[2*p][0]   = tl[0]; Bl[2*p][1]   = tl[1];
                Bl[2*p+1][0] = tl[2]; Bl[2*p+1][1] = tl[3];
            }
            #pragma unroll
            for (int mt = 0; mt < 4; mt++)
                #pragma unroll
                for (int nt = 0; nt < 4; nt++)
                    mma16816(acc[mt][nt], Ah[mt], Bh[nt]);
            #pragma unroll
            for (int mt = 0; mt < 4; mt++)
                #pragma unroll
                for (int nt = 0; nt < 4; nt++)
                    mma16816(acc[mt][nt], Ah[mt], Bl[nt]);
            #pragma unroll
            for (int mt = 0; mt < 4; mt++)
                #pragma unroll
                for (int nt = 0; nt < 4; nt++)
                    mma16816(acc[mt][nt], Al[mt], Bh[nt]);
        }
        __syncthreads();
    }

    float* T = g_tri + (size_t)c*NTOK;
    const int er = i0 + m_base + (lane >> 2);
    const int ec = j0 + n_base + (lane & 3)*2;
    #pragma unroll
    for (int mt = 0; mt < 4; mt++) {
        #pragma unroll
        for (int nt = 0; nt < 4; nt++) {
            int rr = er + mt*16;
            int cc = ec + nt*8;
            *(float2*)&T[(size_t)rr*SDIM + cc]     = make_float2(acc[mt][nt][0], acc[mt][nt][1]);
            *(float2*)&T[(size_t)(rr+8)*SDIM + cc] = make_float2(acc[mt][nt][2], acc[mt][nt][3]);
        }
    }
}

// ---------------------------------------------------------------------------
// Kernel 3: out_persist — persistent; LN(tri) @ w_p_out * gate.
// grid 148, tile = 128 tokens x 128 cout. Prefetch next tri tile during MMA.
// ---------------------------------------------------------------------------
#define OU_STG   0
#define OU_AHI   (128*XROW)            // 67584
#define OU_ALO   (OU_AHI + PTILE)
#define OU_B     (OU_ALO + PTILE)
#define OU_SMEM  (OU_B + 2*PTILE)      // 206848
#define NOTILE   (NTOK/128)            // 4608

__global__ void __launch_bounds__(256) out_persist_kernel(
    const float* __restrict__ now, const float* __restrict__ nob,
    float* __restrict__ out)
{
    extern __shared__ char sm[];
    const uint32_t base = smem_u32(sm);
    const int tid = threadIdx.x;
    const int bid = blockIdx.x;

    // one-time B (wpo^T split)
    const __nv_bfloat16* bsrc[2] = { g_wpoh, g_wpol };
    for (int tile = 0; tile < 2; tile++) {
        #pragma unroll
        for (int rep = 0; rep < 8; rep++) {
            int it = tid + rep*256;
            int row = it >> 4, q = it & 15;
            CP_ASYNC16(base + OU_B + tile*PTILE + row*PROW + q*16,
                       (const char*)(bsrc[tile] + row*128) + q*16);
        }
    }
    // first tri tile
    {
        int t0 = bid * 128;
        #pragma unroll
        for (int rep = 0; rep < 16; rep++) {
            int it = tid + rep*256;
            int ch = it >> 5, q = it & 31;
            CP_ASYNC16(base + OU_STG + ch*XROW + q*16,
                       g_tri + (size_t)ch*NTOK + t0 + q*4);
        }
    }
    CP_COMMIT();

    const int wid  = tid >> 5;
    const int lane = tid & 31;
    const int m_base = (wid >> 2) * 64;
    const int n_base = (wid & 3) * 32;
    const int a_row  = lane & 15;
    const int a_half = lane >> 4;
    const int b_quad = lane >> 3;
    const int b_row  = (b_quad >> 1)*8 + (lane & 7);
    const int b_half = b_quad & 1;
    const int er = m_base + (lane >> 2);
    const int ec = n_base + (lane & 3)*2;

    const float* trs = (const float*)(sm + OU_STG);
    const int tl = tid >> 1, half = tid & 1;

    for (int tile = bid; tile < NOTILE; tile += NSM) {
        const int t0 = tile * 128;
        CP_WAIT0();
        __syncthreads();

        // LN over channels -> split A [t][ch]
        {
            float s = 0.f;
            #pragma unroll 8
            for (int j = 0; j < 64; j++) s += trs[(half*64 + j)*132 + tl];
            s += __shfl_xor_sync(0xFFFFFFFFu, s, 1);
            float m = s * (1.f/128.f);
            float q2 = 0.f;
            #pragma unroll 8
            for (int j = 0; j < 64; j++) {
                float d = trs[(half*64 + j)*132 + tl] - m;
                q2 += d*d;
            }
            q2 += __shfl_xor_sync(0xFFFFFFFFu, q2, 1);
            float rs = rsqrtf(q2 * (1.f/128.f) + 1e-5f);

            #pragma unroll
            for (int j = 0; j < 32; j++) {
                int ch = half*64 + j*2;
                float v0 = (trs[ch*132 + tl]     - m)*rs*__ldg(&now[ch])   + __ldg(&nob[ch]);
                float v1 = (trs[(ch+1)*132 + tl] - m)*rs*__ldg(&now[ch+1]) + __ldg(&nob[ch+1]);
                __nv_bfloat16 h0 = __float2bfloat16(v0);
                __nv_bfloat16 h1 = __float2bfloat16(v1);
                __nv_bfloat162 hh; hh.x = h0; hh.y = h1;
                __nv_bfloat162 ll;
                ll.x = __float2bfloat16(v0 - __bfloat162float(h0));
                ll.y = __float2bfloat16(v1 - __bfloat162float(h1));
                *(__nv_bfloat162*)(sm + OU_AHI + tl*PROW + ch*2) = hh;
                *(__nv_bfloat162*)(sm + OU_ALO + tl*PROW + ch*2) = ll;
            }
        }
        __syncthreads();

        // prefetch next tri tile
        if (tile + NSM < NOTILE) {
            int nt0 = (tile + NSM) * 128;
            #pragma unroll
            for (int rep = 0; rep < 16; rep++) {
                int it = tid + rep*256;
                int ch = it >> 5, q = it & 31;
                CP_ASYNC16(base + OU_STG + ch*XROW + q*16,
                           g_tri + (size_t)ch*NTOK + nt0 + q*4);
            }
        }
        CP_COMMIT();

        float acc[4][4][4];
        #pragma unroll
        for (int mt = 0; mt < 4; mt++)
            #pragma unroll
            for (int nt = 0; nt < 4; nt++)
                #pragma unroll
                for (int r = 0; r < 4; r++) acc[mt][nt][r] = 0.f;

        #pragma unroll
        for (int ks = 0; ks < 8; ks++) {
            const uint32_t koff = ks*32;
            uint32_t Ah[4][4], Al[4][4];
            #pragma unroll
            for (int mt = 0; mt < 4; mt++) {
                uint32_t r = (m_base + mt*16 + a_row)*PROW + koff + a_half*16;
                ldsm4(Ah[mt], base + OU_AHI + r);
                ldsm4(Al[mt], base + OU_ALO + r);
            }
            uint32_t Bh[4][2], Bl[4][2];
            #pragma unroll
            for (int p = 0; p < 2; p++) {
                uint32_t r = (n_base + p*16 + b_row)*PROW + koff + b_half*16;
                uint32_t th[4], tl4[4];
                ldsm4(th,  base + OU_B + 0*PTILE + r);
                ldsm4(tl4, base + OU_B + 1*PTILE + r);
                Bh[2*p][0]=th[0];  Bh[2*p][1]=th[1];  Bh[2*p+1][0]=th[2];  Bh[2*p+1][1]=th[3];
                Bl[2*p][0]=tl4[0]; Bl[2*p][1]=tl4[1]; Bl[2*p+1][0]=tl4[2]; Bl[2*p+1][1]=tl4[3];
            }
            #pragma unroll
            for (int mt = 0; mt < 4; mt++)
                #pragma unroll
                for (int nt = 0; nt < 4; nt++) mma16816(acc[mt][nt], Ah[mt], Bh[nt]);
            #pragma unroll
            for (int mt = 0; mt < 4; mt++)
                #pragma unroll
                for (int nt = 0; nt < 4; nt++) mma16816(acc[mt][nt], Ah[mt], Bl[nt]);
            #pragma unroll
            for (int mt = 0; mt < 4; mt++)
                #pragma unroll
                for (int nt = 0; nt < 4; nt++) mma16816(acc[mt][nt], Al[mt], Bh[nt]);
        }

        #pragma unroll
        for (int mt = 0; mt < 4; mt++) {
            #pragma unroll
            for (int rp = 0; rp < 2; rp++) {
                int t = t0 + er + mt*16 + rp*8;
                #pragma unroll
                for (int nt = 0; nt < 4; nt++) {
                    int cc = ec + nt*8;
                    float2 gg = *(const float2*)&g_gate[(size_t)t*CCH + cc];
                    float2 o = make_float2(acc[mt][nt][rp*2]   * gg.x,
                                           acc[mt][nt][rp*2+1] * gg.y);
                    *(float2*)&out[(size_t)t*CCH + cc] = o;
                }
            }
        }
    }
}

// ---------------------------------------------------------------------------
extern "C" void kernel_launch(void* const* d_in, const int* in_sizes, int n_in,
                              void* d_out, int out_size)
{
    const float* x    = (const float*)d_in[0];
    const float* mask = (const float*)d_in[1];
    const float* niw  = (const float*)d_in[2];
    const float* nib  = (const float*)d_in[3];
    const float* wgi  = (const float*)d_in[4];
    const float* wpi  = (const float*)d_in[5];
    const float* now  = (const float*)d_in[6];
    const float* nob  = (const float*)d_in[7];
    const float* wgo  = (const float*)d_in[8];
    const float* wpo  = (const float*)d_in[9];
    float* out = (float*)d_out;

    cudaFuncSetAttribute(proj_persist_kernel,
        cudaFuncAttributeMaxDynamicSharedMemorySize, PJ_SMEM);
    cudaFuncSetAttribute(tri_mma_kernel,
        cudaFuncAttributeMaxDynamicSharedMemorySize, 2*CHUNKB);
    cudaFuncSetAttribute(out_persist_kernel,
        cudaFuncAttributeMaxDynamicSharedMemorySize, OU_SMEM);

    prep_w_kernel<<<128, 256>>>(wgi, wpi, wgo, wpo);
    proj_persist_kernel<<<dim3(NSM, 3), 256, PJ_SMEM>>>(x, mask, niw, nib);
    tri_mma_kernel<<<dim3(36, 128), 256, 2*CHUNKB>>>();
    out_persist_kernel<<<NSM, 256, OU_SMEM>>>(now, nob, out);
}

// round 6
// speedup vs baseline: 3.0283x; 1.1642x over previous
#include <cuda_runtime.h>
#include <cuda_bf16.h>
#include <cuda_fp16.h>
#include <math.h>
#include <stdint.h>

#define SDIM 768
#define CCH  128
#define NTOK (SDIM*SDIM)        // 589824 tokens
#define SELEM 75497472          // 128 * 589824
#define NSM   148

// Scratch: a as fp16 hi/lo (exact split), b as fp16 hi only
__device__ __half g_ahi[SELEM];
__device__ __half g_alo[SELEM];
__device__ __half g_bhi[SELEM];
__device__ float g_tri[SELEM];
__device__ float g_gate[SELEM];

// Prepped split-bf16 weights, [n][k] layout (k contiguous, 128 per row)
__device__ __nv_bfloat16 g_wgih[256*128], g_wgil[256*128];
__device__ __nv_bfloat16 g_wpih[256*128], g_wpil[256*128];
__device__ __nv_bfloat16 g_wgoh[128*128], g_wgol[128*128];
__device__ __nv_bfloat16 g_wpoh[128*128], g_wpol[128*128];

__device__ __forceinline__ float sigmoidf_(float v) {
    return 1.f / (1.f + __expf(-v));
}
__device__ __forceinline__ uint32_t smem_u32(const void* p) {
    uint32_t a;
    asm("{ .reg .u64 t; cvta.to.shared.u64 t, %1; cvt.u32.u64 %0, t; }"
        : "=r"(a) : "l"(p));
    return a;
}
#define CP_ASYNC16(d, s)  asm volatile("cp.async.cg.shared.global [%0], [%1], 16;" :: "r"(d), "l"(s))
#define CP_COMMIT()       asm volatile("cp.async.commit_group;" ::: "memory")
#define CP_WAIT0()        asm volatile("cp.async.wait_group 0;" ::: "memory")
#define CP_WAIT2()        asm volatile("cp.async.wait_group 2;" ::: "memory")

__device__ __forceinline__ void ldsm4(uint32_t* r, uint32_t addr) {
    asm volatile("ldmatrix.sync.aligned.m8n8.x4.shared.b16 {%0,%1,%2,%3}, [%4];"
        : "=r"(r[0]), "=r"(r[1]), "=r"(r[2]), "=r"(r[3]) : "r"(addr));
}
// bf16 HMMA
__device__ __forceinline__ void mma16816(float* d, const uint32_t* a, const uint32_t* b) {
    asm volatile("mma.sync.aligned.m16n8k16.row.col.f32.bf16.bf16.f32 "
        "{%0,%1,%2,%3}, {%4,%5,%6,%7}, {%8,%9}, {%0,%1,%2,%3};"
        : "+f"(d[0]), "+f"(d[1]), "+f"(d[2]), "+f"(d[3])
        : "r"(a[0]), "r"(a[1]), "r"(a[2]), "r"(a[3]), "r"(b[0]), "r"(b[1]));
}
// fp16 HMMA
__device__ __forceinline__ void mma16816h(float* d, const uint32_t* a, const uint32_t* b) {
    asm volatile("mma.sync.aligned.m16n8k16.row.col.f32.f16.f16.f32 "
        "{%0,%1,%2,%3}, {%4,%5,%6,%7}, {%8,%9}, {%0,%1,%2,%3};"
        : "+f"(d[0]), "+f"(d[1]), "+f"(d[2]), "+f"(d[3])
        : "r"(a[0]), "r"(a[1]), "r"(a[2]), "r"(a[3]), "r"(b[0]), "r"(b[1]));
}
__device__ __forceinline__ uint32_t pack_split16(float v) {
    __half h = __float2half_rn(v);
    __half l = __float2half_rn(v - __half2float(h));
    return (uint32_t)__half_as_ushort(h) | ((uint32_t)__half_as_ushort(l) << 16);
}

// ---------------------------------------------------------------------------
// Kernel 0: weight prep — transpose + split to bf16 hi/lo, [n][k].
// ---------------------------------------------------------------------------
__global__ void __launch_bounds__(256) prep_w_kernel(
    const float* __restrict__ wgi, const float* __restrict__ wpi,
    const float* __restrict__ wgo, const float* __restrict__ wpo)
{
    int idx = blockIdx.x*256 + threadIdx.x;   // 0..32767
    int n = idx >> 7, k = idx & 127;

    float v = wgi[k*256 + n];
    __nv_bfloat16 h = __float2bfloat16(v);
    g_wgih[idx] = h;
    g_wgil[idx] = __float2bfloat16(v - __bfloat162float(h));

    v = wpi[k*256 + n];
    h = __float2bfloat16(v);
    g_wpih[idx] = h;
    g_wpil[idx] = __float2bfloat16(v - __bfloat162float(h));

    if (n < 128) {
        v = wgo[k*128 + n];
        h = __float2bfloat16(v);
        g_wgoh[idx] = h;
        g_wgol[idx] = __float2bfloat16(v - __bfloat162float(h));

        v = wpo[k*128 + n];   // B = wpo^T : [co=n][h=k]
        h = __float2bfloat16(v);
        g_wpoh[idx] = h;
        g_wpol[idx] = __float2bfloat16(v - __bfloat162float(h));
    }
}

// ---------------------------------------------------------------------------
// Kernel 1: proj_persist — persistent; LN(x) + projections via split HMMA.
// grid (148, 3): job0 = a channels, job1 = b channels, job2 = out-gate.
// ---------------------------------------------------------------------------
#define PROW   272
#define PTILE  (128*PROW)         // 34816
#define ATILE  (64*PROW)          // 17408
#define XROW   528
#define PJ_AHI   0
#define PJ_ALO   ATILE
#define PJ_B     (2*ATILE)
#define PJ_STG   (PJ_B + 4*PTILE)
#define PJ_SMEM  (PJ_STG + 64*XROW)        // 207872
#define NPTILE   (NTOK/64)                 // 9216

__global__ void __launch_bounds__(256) proj_persist_kernel(
    const float* __restrict__ x, const float* __restrict__ mask,
    const float* __restrict__ nw, const float* __restrict__ nb)
{
    extern __shared__ char sm[];
    const uint32_t base = smem_u32(sm);
    const int tid = threadIdx.x;
    const int bid = blockIdx.x;
    const int job = blockIdx.y;

    const __nv_bfloat16* bsrc[4];
    int ntiles;
    if (job < 2) {
        bsrc[0] = g_wgih + job*128*128; bsrc[1] = g_wgil + job*128*128;
        bsrc[2] = g_wpih + job*128*128; bsrc[3] = g_wpil + job*128*128;
        ntiles = 4;
    } else {
        bsrc[0] = g_wgoh; bsrc[1] = g_wgol;
        ntiles = 2;
    }
    for (int tile = 0; tile < ntiles; tile++) {
        #pragma unroll
        for (int rep = 0; rep < 8; rep++) {
            int it  = tid + rep*256;
            int row = it >> 4, q = it & 15;
            CP_ASYNC16(base + PJ_B + tile*PTILE + row*PROW + q*16,
                       (const char*)(bsrc[tile] + row*128) + q*16);
        }
    }
    {
        int t0 = bid * 64;
        #pragma unroll
        for (int rep = 0; rep < 8; rep++) {
            int it = tid + rep*256;
            int row = it >> 5, q = it & 31;
            CP_ASYNC16(base + PJ_STG + row*XROW + q*16,
                       x + (size_t)(t0 + row)*CCH + q*4);
        }
    }
    CP_COMMIT();

    const int wid  = tid >> 5;
    const int lane = tid & 31;
    const int m_base = (wid >> 2) * 32;
    const int n_base = (wid & 3) * 32;
    const int a_row  = lane & 15;
    const int a_half = lane >> 4;
    const int b_quad = lane >> 3;
    const int b_row  = (b_quad >> 1)*8 + (lane & 7);
    const int b_half = b_quad & 1;
    const int ec = n_base + (lane & 3)*2;

    const float* xstg = (const float*)(sm + PJ_STG);
    const int tl = tid >> 2, qq = tid & 3;

    for (int tile = bid; tile < NPTILE; tile += NSM) {
        const int t0 = tile * 64;
        CP_WAIT0();
        __syncthreads();

        {
            float v[32];
            float s = 0.f;
            #pragma unroll
            for (int i = 0; i < 8; i++) {
                float4 f = *(const float4*)&xstg[tl*132 + qq*32 + i*4];
                v[i*4]=f.x; v[i*4+1]=f.y; v[i*4+2]=f.z; v[i*4+3]=f.w;
                s += f.x + f.y + f.z + f.w;
            }
            s += __shfl_xor_sync(0xFFFFFFFFu, s, 1);
            s += __shfl_xor_sync(0xFFFFFFFFu, s, 2);
            float m = s * (1.f/128.f);
            float q2 = 0.f;
            #pragma unroll
            for (int i = 0; i < 32; i++) { float d = v[i]-m; q2 += d*d; }
            q2 += __shfl_xor_sync(0xFFFFFFFFu, q2, 1);
            q2 += __shfl_xor_sync(0xFFFFFFFFu, q2, 2);
            float rs = rsqrtf(q2 * (1.f/128.f) + 1e-5f);

            #pragma unroll
            for (int i = 0; i < 16; i++) {
                int k = qq*32 + i*2;
                float v0 = (v[i*2]   - m)*rs*__ldg(&nw[k])   + __ldg(&nb[k]);
                float v1 = (v[i*2+1] - m)*rs*__ldg(&nw[k+1]) + __ldg(&nb[k+1]);
                __nv_bfloat16 h0 = __float2bfloat16(v0);
                __nv_bfloat16 h1 = __float2bfloat16(v1);
                __nv_bfloat162 hh; hh.x = h0; hh.y = h1;
                __nv_bfloat162 ll;
                ll.x = __float2bfloat16(v0 - __bfloat162float(h0));
                ll.y = __float2bfloat16(v1 - __bfloat162float(h1));
                *(__nv_bfloat162*)(sm + PJ_AHI + tl*PROW + k*2) = hh;
                *(__nv_bfloat162*)(sm + PJ_ALO + tl*PROW + k*2) = ll;
            }
        }
        __syncthreads();

        if (tile + NSM < NPTILE) {
            int nt0 = (tile + NSM) * 64;
            #pragma unroll
            for (int rep = 0; rep < 8; rep++) {
                int it = tid + rep*256;
                int row = it >> 5, q = it & 31;
                CP_ASYNC16(base + PJ_STG + row*XROW + q*16,
                           x + (size_t)(nt0 + row)*CCH + q*4);
            }
        }
        CP_COMMIT();

        if (job < 2) {
            float accg[2][4][4], accp[2][4][4];
            #pragma unroll
            for (int mt = 0; mt < 2; mt++)
                #pragma unroll
                for (int nt = 0; nt < 4; nt++)
                    #pragma unroll
                    for (int r = 0; r < 4; r++) { accg[mt][nt][r]=0.f; accp[mt][nt][r]=0.f; }

            #pragma unroll
            for (int ks = 0; ks < 8; ks++) {
                const uint32_t koff = ks*32;
                uint32_t Ah[2][4], Al[2][4];
                #pragma unroll
                for (int mt = 0; mt < 2; mt++) {
                    uint32_t r = (m_base + mt*16 + a_row)*PROW + koff + a_half*16;
                    ldsm4(Ah[mt], base + PJ_AHI + r);
                    ldsm4(Al[mt], base + PJ_ALO + r);
                }
                #pragma unroll
                for (int g = 0; g < 2; g++) {
                    uint32_t Bh[4][2], Bl[4][2];
                    #pragma unroll
                    for (int p = 0; p < 2; p++) {
                        uint32_t r = (n_base + p*16 + b_row)*PROW + koff + b_half*16;
                        uint32_t th[4], tl4[4];
                        ldsm4(th,  base + PJ_B + (2*g+0)*PTILE + r);
                        ldsm4(tl4, base + PJ_B + (2*g+1)*PTILE + r);
                        Bh[2*p][0]=th[0];  Bh[2*p][1]=th[1];  Bh[2*p+1][0]=th[2];  Bh[2*p+1][1]=th[3];
                        Bl[2*p][0]=tl4[0]; Bl[2*p][1]=tl4[1]; Bl[2*p+1][0]=tl4[2]; Bl[2*p+1][1]=tl4[3];
                    }
                    float (*acc)[4][4] = g ? accp : accg;
                    #pragma unroll
                    for (int mt = 0; mt < 2; mt++)
                        #pragma unroll
                        for (int nt = 0; nt < 4; nt++) mma16816(acc[mt][nt], Ah[mt], Bh[nt]);
                    #pragma unroll
                    for (int mt = 0; mt < 2; mt++)
                        #pragma unroll
                        for (int nt = 0; nt < 4; nt++) mma16816(acc[mt][nt], Ah[mt], Bl[nt]);
                    #pragma unroll
                    for (int mt = 0; mt < 2; mt++)
                        #pragma unroll
                        for (int nt = 0; nt < 4; nt++) mma16816(acc[mt][nt], Al[mt], Bh[nt]);
                }
            }
            __syncthreads();

            // transpose via smem: fp16 split packed u32 at [c][t]
            uint32_t* tp = (uint32_t*)(sm + PJ_AHI);
            #pragma unroll
            for (int mt = 0; mt < 2; mt++) {
                #pragma unroll
                for (int rp = 0; rp < 2; rp++) {
                    int t_loc = m_base + mt*16 + rp*8 + (lane >> 2);
                    float mk = (job == 0) ? __ldg(&mask[t0 + t_loc]) : 1.f;
                    #pragma unroll
                    for (int nt = 0; nt < 4; nt++) {
                        #pragma unroll
                        for (int e = 0; e < 2; e++) {
                            int c = ec + nt*8 + e;
                            float val = sigmoidf_(accg[mt][nt][rp*2+e]) * accp[mt][nt][rp*2+e] * mk;
                            tp[c*68 + t_loc] = pack_split16(val);
                        }
                    }
                }
            }
            __syncthreads();

            if (job == 0) {
                uint32_t* dHi = (uint32_t*)g_ahi;
                uint32_t* dLo = (uint32_t*)g_alo;
                #pragma unroll
                for (int rep = 0; rep < 16; rep++) {
                    int idx = tid + rep*256;
                    int c = idx >> 5, t2 = idx & 31;
                    uint32_t u0 = tp[c*68 + t2*2];
                    uint32_t u1 = tp[c*68 + t2*2 + 1];
                    size_t o = ((size_t)c*NTOK + t0) >> 1;
                    dHi[o + t2] = (u0 & 0xFFFFu) | (u1 << 16);
                    dLo[o + t2] = (u0 >> 16) | (u1 & 0xFFFF0000u);
                }
            } else {
                uint32_t* dHi = (uint32_t*)g_bhi;
                #pragma unroll
                for (int rep = 0; rep < 16; rep++) {
                    int idx = tid + rep*256;
                    int c = idx >> 5, t2 = idx & 31;
                    uint32_t u0 = tp[c*68 + t2*2];
                    uint32_t u1 = tp[c*68 + t2*2 + 1];
                    size_t o = ((size_t)c*NTOK + t0) >> 1;
                    dHi[o + t2] = (u0 & 0xFFFFu) | (u1 << 16);
                }
            }
        } else {
            float acc[2][4][4];
            #pragma unroll
            for (int mt = 0; mt < 2; mt++)
                #pragma unroll
                for (int nt = 0; nt < 4; nt++)
                    #pragma unroll
                    for (int r = 0; r < 4; r++) acc[mt][nt][r] = 0.f;

            #pragma unroll
            for (int ks = 0; ks < 8; ks++) {
                const uint32_t koff = ks*32;
                uint32_t Ah[2][4], Al[2][4];
                #pragma unroll
                for (int mt = 0; mt < 2; mt++) {
                    uint32_t r = (m_base + mt*16 + a_row)*PROW + koff + a_half*16;
                    ldsm4(Ah[mt], base + PJ_AHI + r);
                    ldsm4(Al[mt], base + PJ_ALO + r);
                }
                uint32_t Bh[4][2], Bl[4][2];
                #pragma unroll
                for (int p = 0; p < 2; p++) {
                    uint32_t r = (n_base + p*16 + b_row)*PROW + koff + b_half*16;
                    uint32_t th[4], tl4[4];
                    ldsm4(th,  base + PJ_B + 0*PTILE + r);
                    ldsm4(tl4, base + PJ_B + 1*PTILE + r);
                    Bh[2*p][0]=th[0];  Bh[2*p][1]=th[1];  Bh[2*p+1][0]=th[2];  Bh[2*p+1][1]=th[3];
                    Bl[2*p][0]=tl4[0]; Bl[2*p][1]=tl4[1]; Bl[2*p+1][0]=tl4[2]; Bl[2*p+1][1]=tl4[3];
                }
                #pragma unroll
                for (int mt = 0; mt < 2; mt++)
                    #pragma unroll
                    for (int nt = 0; nt < 4; nt++) mma16816(acc[mt][nt], Ah[mt], Bh[nt]);
                #pragma unroll
                for (int mt = 0; mt < 2; mt++)
                    #pragma unroll
                    for (int nt = 0; nt < 4; nt++) mma16816(acc[mt][nt], Ah[mt], Bl[nt]);
                #pragma unroll
                for (int mt = 0; mt < 2; mt++)
                    #pragma unroll
                    for (int nt = 0; nt < 4; nt++) mma16816(acc[mt][nt], Al[mt], Bh[nt]);
            }

            #pragma unroll
            for (int mt = 0; mt < 2; mt++) {
                #pragma unroll
                for (int rp = 0; rp < 2; rp++) {
                    int t = t0 + m_base + mt*16 + rp*8 + (lane >> 2);
                    #pragma unroll
                    for (int nt = 0; nt < 4; nt++) {
                        int c = ec + nt*8;
                        float2 f = make_float2(sigmoidf_(acc[mt][nt][rp*2]),
                                               sigmoidf_(acc[mt][nt][rp*2+1]));
                        *(float2*)&g_gate[(size_t)t*CCH + c] = f;
                    }
                }
            }
            __syncthreads();
        }
    }
}

// ---------------------------------------------------------------------------
// Kernel 2: tri einsum, 2-pass split-fp16 (Ah+Al vs Bh), triple-buffered.
// ---------------------------------------------------------------------------
#define ROWB    144
#define TILEB   (128*ROWB)          // 18432
#define CHUNK3  (3*TILEB)           // 55296

__device__ __forceinline__ void tri_load_chunk(
    uint32_t sbuf, const __half* s0, const __half* s1, const __half* s2,
    int kk, int tid)
{
    const __half* srcs[3] = {s0, s1, s2};
    #pragma unroll
    for (int rep = 0; rep < 12; rep++) {
        int it   = tid + rep*256;             // 0..3071
        int tile = it >> 10;
        int row  = (it >> 3) & 127;
        int q8   = it & 7;
        const __half* gp = srcs[tile] + (size_t)row*SDIM + kk + q8*8;
        CP_ASYNC16(sbuf + tile*TILEB + row*ROWB + q8*16, gp);
    }
}

__global__ void __launch_bounds__(256) tri_mma_kernel()
{
    extern __shared__ char dynsm[];
    const uint32_t base = smem_u32(dynsm);

    const int tid  = threadIdx.x;
    const int wid  = tid >> 5;
    const int lane = tid & 31;
    const int m_base = (wid >> 2) * 64;
    const int n_base = (wid & 3) * 32;

    const int c  = blockIdx.y;
    const int i0 = (blockIdx.x / 6) * 128;
    const int j0 = (blockIdx.x % 6) * 128;

    const __half* sAh = g_ahi + (size_t)c*NTOK + (size_t)i0*SDIM;
    const __half* sAl = g_alo + (size_t)c*NTOK + (size_t)i0*SDIM;
    const __half* sBh = g_bhi + (size_t)c*NTOK + (size_t)j0*SDIM;

    float acc[4][4][4];
    #pragma unroll
    for (int mt = 0; mt < 4; mt++)
        #pragma unroll
        for (int nt = 0; nt < 4; nt++)
            #pragma unroll
            for (int r = 0; r < 4; r++) acc[mt][nt][r] = 0.f;

    const int a_row  = lane & 15;
    const int a_half = lane >> 4;
    const int b_quad = lane >> 3;
    const int b_row  = (b_quad >> 1) * 8 + (lane & 7);
    const int b_half = b_quad & 1;

    tri_load_chunk(base + 0*CHUNK3, sAh, sAl, sBh, 0,  tid); CP_COMMIT();
    tri_load_chunk(base + 1*CHUNK3, sAh, sAl, sBh, 64, tid); CP_COMMIT();

    for (int n = 0; n < 12; n++) {
        if (n + 2 < 12)
            tri_load_chunk(base + ((n+2)%3)*CHUNK3, sAh, sAl, sBh, (n+2)*64, tid);
        CP_COMMIT();
        CP_WAIT2();
        __syncthreads();

        const uint32_t sb = base + (n%3)*CHUNK3;
        #pragma unroll
        for (int ks = 0; ks < 4; ks++) {
            uint32_t Ah[4][4], Al[4][4], Bh[4][2];
            const uint32_t koff = ks*32;
            #pragma unroll
            for (int mt = 0; mt < 4; mt++) {
                uint32_t r = (m_base + mt*16 + a_row)*ROWB + koff + a_half*16;
                ldsm4(Ah[mt], sb + 0*TILEB + r);
                ldsm4(Al[mt], sb + 1*TILEB + r);
            }
            #pragma unroll
            for (int p = 0; p < 2; p++) {
                uint32_t r = (n_base + p*16 + b_row)*ROWB + koff + b_half*16;
                uint32_t th[4];
                ldsm4(th, sb + 2*TILEB + r);
                Bh[2*p][0]   = th[0]; Bh[2*p][1]   = th[1];
                Bh[2*p+1][0] = th[2]; Bh[2*p+1][1] = th[3];
            }
            #pragma unroll
            for (int mt = 0; mt < 4; mt++)
                #pragma unroll
                for (int nt = 0; nt < 4; nt++)
                    mma16816h(acc[mt][nt], Ah[mt], Bh[nt]);
            #pragma unroll
            for (int mt = 0; mt < 4; mt++)
                #pragma unroll
                for (int nt = 0; nt < 4; nt++)
                    mma16816h(acc[mt][nt], Al[mt], Bh[nt]);
        }
        __syncthreads();
    }

    float* T = g_tri + (size_t)c*NTOK;
    const int er = i0 + m_base + (lane >> 2);
    const int ec2 = j0 + n_base + (lane & 3)*2;
    #pragma unroll
    for (int mt = 0; mt < 4; mt++) {
        #pragma unroll
        for (int nt = 0; nt < 4; nt++) {
            int rr = er + mt*16;
            int cc = ec2 + nt*8;
            *(float2*)&T[(size_t)rr*SDIM + cc]     = make_float2(acc[mt][nt][0], acc[mt][nt][1]);
            *(float2*)&T[(size_t)(rr+8)*SDIM + cc] = make_float2(acc[mt][nt][2], acc[mt][nt][3]);
        }
    }
}

// ---------------------------------------------------------------------------
// Kernel 3: out_persist v2 — 64-token tiles, staged tri+gate, prefetch-next.
// ---------------------------------------------------------------------------
#define OV_TRI   0                      // 128 x 272B  (tri [ch][t] f32)
#define OV_G0    34816                  // 64 x 528B   (gate [t][c] f32)
#define OV_G1    (OV_G0 + 33792)
#define OV_AHI   (OV_G1 + 33792)        // 64 x 272B
#define OV_ALO   (OV_AHI + ATILE)
#define OV_B     (OV_ALO + ATILE)       // 2 x 34816
#define OV_SMEM  (OV_B + 2*PTILE)       // 206848
#define NOTILE64 (NTOK/64)              // 9216

__global__ void __launch_bounds__(256) out_persist_kernel(
    const float* __restrict__ now, const float* __restrict__ nob,
    float* __restrict__ out)
{
    extern __shared__ char sm[];
    const uint32_t base = smem_u32(sm);
    const int tid = threadIdx.x;
    const int bid = blockIdx.x;

    // one-time B (wpo^T split bf16)
    const __nv_bfloat16* bsrc[2] = { g_wpoh, g_wpol };
    for (int tile = 0; tile < 2; tile++) {
        #pragma unroll
        for (int rep = 0; rep < 8; rep++) {
            int it = tid + rep*256;
            int row = it >> 4, q = it & 15;
            CP_ASYNC16(base + OV_B + tile*PTILE + row*PROW + q*16,
                       (const char*)(bsrc[tile] + row*128) + q*16);
        }
    }
    // first tile: tri + gate
    {
        int t0 = bid * 64;
        #pragma unroll
        for (int rep = 0; rep < 8; rep++) {
            int it = tid + rep*256;
            int ch = it >> 4, q = it & 15;
            CP_ASYNC16(base + OV_TRI + ch*272 + q*16,
                       g_tri + (size_t)ch*NTOK + t0 + q*4);
        }
        #pragma unroll
        for (int rep = 0; rep < 8; rep++) {
            int it = tid + rep*256;
            int row = it >> 5, q = it & 31;
            CP_ASYNC16(base + OV_G0 + row*528 + q*16,
                       g_gate + (size_t)(t0 + row)*CCH + q*4);
        }
    }
    CP_COMMIT();

    const int wid  = tid >> 5;
    const int lane = tid & 31;
    const int m_base = (wid >> 2) * 32;
    const int n_base = (wid & 3) * 32;
    const int a_row  = lane & 15;
    const int a_half = lane >> 4;
    const int b_quad = lane >> 3;
    const int b_row  = (b_quad >> 1)*8 + (lane & 7);
    const int b_half = b_quad & 1;
    const int er = m_base + (lane >> 2);
    const int ec = n_base + (lane & 3)*2;

    const float* trs = (const float*)(sm + OV_TRI);
    const int tl = tid >> 2, qq = tid & 3;

    int ii = 0;
    for (int tile = bid; tile < NOTILE64; tile += NSM, ii++) {
        const int t0 = tile * 64;
        const int gbuf = ii & 1;
        CP_WAIT0();
        __syncthreads();

        // LN over channels -> split-bf16 A [t][ch]
        {
            float s = 0.f;
            #pragma unroll 8
            for (int j = 0; j < 32; j++) s += trs[(qq*32 + j)*68 + tl];
            s += __shfl_xor_sync(0xFFFFFFFFu, s, 1);
            s += __shfl_xor_sync(0xFFFFFFFFu, s, 2);
            float m = s * (1.f/128.f);
            float q2 = 0.f;
            #pragma unroll 8
            for (int j = 0; j < 32; j++) {
                float d = trs[(qq*32 + j)*68 + tl] - m;
                q2 += d*d;
            }
            q2 += __shfl_xor_sync(0xFFFFFFFFu, q2, 1);
            q2 += __shfl_xor_sync(0xFFFFFFFFu, q2, 2);
            float rs = rsqrtf(q2 * (1.f/128.f) + 1e-5f);

            #pragma unroll
            for (int j = 0; j < 16; j++) {
                int ch = qq*32 + j*2;
                float v0 = (trs[ch*68 + tl]     - m)*rs*__ldg(&now[ch])   + __ldg(&nob[ch]);
                float v1 = (trs[(ch+1)*68 + tl] - m)*rs*__ldg(&now[ch+1]) + __ldg(&nob[ch+1]);
                __nv_bfloat16 h0 = __float2bfloat16(v0);
                __nv_bfloat16 h1 = __float2bfloat16(v1);
                __nv_bfloat162 hh; hh.x = h0; hh.y = h1;
                __nv_bfloat162 ll;
                ll.x = __float2bfloat16(v0 - __bfloat162float(h0));
                ll.y = __float2bfloat16(v1 - __bfloat162float(h1));
                *(__nv_bfloat162*)(sm + OV_AHI + tl*PROW + ch*2) = hh;
                *(__nv_bfloat162*)(sm + OV_ALO + tl*PROW + ch*2) = ll;
            }
        }
        __syncthreads();

        // prefetch next tri + gate (other gate buffer)
        if (tile + NSM < NOTILE64) {
            int nt0 = (tile + NSM) * 64;
            #pragma unroll
            for (int rep = 0; rep < 8; rep++) {
                int it = tid + rep*256;
                int ch = it >> 4, q = it & 15;
                CP_ASYNC16(base + OV_TRI + ch*272 + q*16,
                           g_tri + (size_t)ch*NTOK + nt0 + q*4);
            }
            uint32_t gdst = base + (gbuf ? OV_G0 : OV_G1);
            #pragma unroll
            for (int rep = 0; rep < 8; rep++) {
                int it = tid + rep*256;
                int row = it >> 5, q = it & 31;
                CP_ASYNC16(gdst + row*528 + q*16,
                           g_gate + (size_t)(nt0 + row)*CCH + q*4);
            }
        }
        CP_COMMIT();

        float acc[2][4][4];
        #pragma unroll
        for (int mt = 0; mt < 2; mt++)
            #pragma unroll
            for (int nt = 0; nt < 4; nt++)
                #pragma unroll
                for (int r = 0; r < 4; r++) acc[mt][nt][r] = 0.f;

        #pragma unroll
        for (int ks = 0; ks < 8; ks++) {
            const uint32_t koff = ks*32;
            uint32_t Ah[2][4], Al[2][4];
            #pragma unroll
            for (int mt = 0; mt < 2; mt++) {
                uint32_t r = (m_base + mt*16 + a_row)*PROW + koff + a_half*16;
                ldsm4(Ah[mt], base + OV_AHI + r);
                ldsm4(Al[mt], base + OV_ALO + r);
            }
            uint32_t Bh[4][2], Bl[4][2];
            #pragma unroll
            for (int p = 0; p < 2; p++) {
                uint32_t r = (n_base + p*16 + b_row)*PROW + koff + b_half*16;
                uint32_t th[4], tl4[4];
                ldsm4(th,  base + OV_B + 0*PTILE + r);
                ldsm4(tl4, base + OV_B + 1*PTILE + r);
                Bh[2*p][0]=th[0];  Bh[2*p][1]=th[1];  Bh[2*p+1][0]=th[2];  Bh[2*p+1][1]=th[3];
                Bl[2*p][0]=tl4[0]; Bl[2*p][1]=tl4[1]; Bl[2*p+1][0]=tl4[2]; Bl[2*p+1][1]=tl4[3];
            }
            #pragma unroll
            for (int mt = 0; mt < 2; mt++)
                #pragma unroll
                for (int nt = 0; nt < 4; nt++) mma16816(acc[mt][nt], Ah[mt], Bh[nt]);
            #pragma unroll
            for (int mt = 0; mt < 2; mt++)
                #pragma unroll
                for (int nt = 0; nt < 4; nt++) mma16816(acc[mt][nt], Ah[mt], Bl[nt]);
            #pragma unroll
            for (int mt = 0; mt < 2; mt++)
                #pragma unroll
                for (int nt = 0; nt < 4; nt++) mma16816(acc[mt][nt], Al[mt], Bh[nt]);
        }

        const float* gst = (const float*)(sm + (gbuf ? OV_G1 : OV_G0));
        #pragma unroll
        for (int mt = 0; mt < 2; mt++) {
            #pragma unroll
            for (int rp = 0; rp < 2; rp++) {
                int t_loc = er + mt*16 + rp*8;
                #pragma unroll
                for (int nt = 0; nt < 4; nt++) {
                    int cc = ec + nt*8;
                    float2 gg = *(const float2*)&gst[t_loc*132 + cc];
                    float2 o = make_float2(acc[mt][nt][rp*2]   * gg.x,
                                           acc[mt][nt][rp*2+1] * gg.y);
                    *(float2*)&out[(size_t)(t0 + t_loc)*CCH + cc] = o;
                }
            }
        }
        __syncthreads();   // protect A/staging before next iteration's writes
    }
}

// ---------------------------------------------------------------------------
extern "C" void kernel_launch(void* const* d_in, const int* in_sizes, int n_in,
                              void* d_out, int out_size)
{
    const float* x    = (const float*)d_in[0];
    const float* mask = (const float*)d_in[1];
    const float* niw  = (const float*)d_in[2];
    const float* nib  = (const float*)d_in[3];
    const float* wgi  = (const float*)d_in[4];
    const float* wpi  = (const float*)d_in[5];
    const float* now  = (const float*)d_in[6];
    const float* nob  = (const float*)d_in[7];
    const float* wgo  = (const float*)d_in[8];
    const float* wpo  = (const float*)d_in[9];
    float* out = (float*)d_out;

    cudaFuncSetAttribute(proj_persist_kernel,
        cudaFuncAttributeMaxDynamicSharedMemorySize, PJ_SMEM);
    cudaFuncSetAttribute(tri_mma_kernel,
        cudaFuncAttributeMaxDynamicSharedMemorySize, 3*CHUNK3);
    cudaFuncSetAttribute(out_persist_kernel,
        cudaFuncAttributeMaxDynamicSharedMemorySize, OV_SMEM);

    prep_w_kernel<<<128, 256>>>(wgi, wpi, wgo, wpo);
    proj_persist_kernel<<<dim3(NSM, 3), 256, PJ_SMEM>>>(x, mask, niw, nib);
    tri_mma_kernel<<<dim3(36, 128), 256, 3*CHUNK3>>>();
    out_persist_kernel<<<NSM, 256, OV_SMEM>>>(now, nob, out);
}

// round 7
// speedup vs baseline: 3.6042x; 1.1902x over previous
#include <cuda_runtime.h>
#include <cuda_bf16.h>
#include <cuda_fp16.h>
#include <math.h>
#include <stdint.h>

#define SDIM 768
#define CCH  128
#define NTOK (SDIM*SDIM)        // 589824 tokens
#define SELEM 75497472          // 128 * 589824
#define NSM   148

// Scratch: a as fp16 hi/lo (exact split), b as fp16 hi only
__device__ __half g_ahi[SELEM];
__device__ __half g_alo[SELEM];
__device__ __half g_bhi[SELEM];
__device__ float g_tri[SELEM];
__device__ float g_gate[SELEM];

// Prepped fp16 weights:
// g_wcI: 4 groups x 128 rows x 128 k; group g row 2r = wgi col(64g+r), row 2r+1 = wpi col(64g+r)
__device__ __half g_wcI[4*128*128];
__device__ __half g_wgo16[128*128];   // wgo^T [n][k]
__device__ __half g_wpo16[128*128];   // wpo^T [co][h]

__device__ __forceinline__ float sigmoidf_(float v) {
    return 1.f / (1.f + __expf(-v));
}
__device__ __forceinline__ uint32_t smem_u32(const void* p) {
    uint32_t a;
    asm("{ .reg .u64 t; cvta.to.shared.u64 t, %1; cvt.u32.u64 %0, t; }"
        : "=r"(a) : "l"(p));
    return a;
}
#define CP_ASYNC16(d, s)  asm volatile("cp.async.cg.shared.global [%0], [%1], 16;" :: "r"(d), "l"(s))
#define CP_COMMIT()       asm volatile("cp.async.commit_group;" ::: "memory")
#define CP_WAIT0()        asm volatile("cp.async.wait_group 0;" ::: "memory")
#define CP_WAIT1()        asm volatile("cp.async.wait_group 1;" ::: "memory")
#define CP_WAIT2()        asm volatile("cp.async.wait_group 2;" ::: "memory")

__device__ __forceinline__ void ldsm4(uint32_t* r, uint32_t addr) {
    asm volatile("ldmatrix.sync.aligned.m8n8.x4.shared.b16 {%0,%1,%2,%3}, [%4];"
        : "=r"(r[0]), "=r"(r[1]), "=r"(r[2]), "=r"(r[3]) : "r"(addr));
}
__device__ __forceinline__ void mma16816h(float* d, const uint32_t* a, const uint32_t* b) {
    asm volatile("mma.sync.aligned.m16n8k16.row.col.f32.f16.f16.f32 "
        "{%0,%1,%2,%3}, {%4,%5,%6,%7}, {%8,%9}, {%0,%1,%2,%3};"
        : "+f"(d[0]), "+f"(d[1]), "+f"(d[2]), "+f"(d[3])
        : "r"(a[0]), "r"(a[1]), "r"(a[2]), "r"(a[3]), "r"(b[0]), "r"(b[1]));
}
__device__ __forceinline__ uint32_t pack_split16(float v) {
    __half h = __float2half_rn(v);
    __half l = __float2half_rn(v - __half2float(h));
    return (uint32_t)__half_as_ushort(h) | ((uint32_t)__half_as_ushort(l) << 16);
}

// ---------------------------------------------------------------------------
// Kernel 0: weight prep.
// ---------------------------------------------------------------------------
__global__ void __launch_bounds__(256) prep_w_kernel(
    const float* __restrict__ wgi, const float* __restrict__ wpi,
    const float* __restrict__ wgo, const float* __restrict__ wpo)
{
    int idx = blockIdx.x*256 + threadIdx.x;   // 0..65535
    {
        int g = idx >> 14, rem = idx & 16383;
        int row = rem >> 7, k = rem & 127;
        int col = g*64 + (row >> 1);
        float v = (row & 1) ? wpi[k*256 + col] : wgi[k*256 + col];
        g_wcI[idx] = __float2half_rn(v);
    }
    if (idx < 16384) {
        int n = idx >> 7, k = idx & 127;
        g_wgo16[idx] = __float2half_rn(wgo[k*128 + n]);
        g_wpo16[idx] = __float2half_rn(wpo[k*128 + n]);
    }
}

// ---------------------------------------------------------------------------
// Kernel 1: proj2 — persistent single-wave; LN(x) + all projections.
// Per 64-token tile: 5 B-chunks streamed from L2 (double buffer), 2-pass fp16.
// ---------------------------------------------------------------------------
#define PROW   272
#define PTILE  (128*PROW)         // 34816
#define ATILE  (64*PROW)          // 17408
#define XROW   528
#define P2_AHI  0
#define P2_ALO  ATILE
#define P2_B    (2*ATILE)                  // 34816
#define P2_STG  (P2_B + 2*PTILE)           // 104448
#define P2_TP   (P2_STG + 64*XROW)         // 138240
#define P2_SMEM (P2_TP + 64*68*4)          // 155648
#define NPTILE  (NTOK/64)                  // 9216

__global__ void __launch_bounds__(256) proj2_kernel(
    const float* __restrict__ x, const float* __restrict__ mask,
    const float* __restrict__ nw, const float* __restrict__ nb)
{
    extern __shared__ char sm[];
    const uint32_t base = smem_u32(sm);
    const int tid = threadIdx.x;
    const int bid = blockIdx.x;

    const int wid  = tid >> 5;
    const int lane = tid & 31;
    const int m_base = (wid >> 2) * 32;
    const int n_base = (wid & 3) * 32;
    const int a_row  = lane & 15;
    const int a_half = lane >> 4;
    const int b_quad = lane >> 3;
    const int b_row  = (b_quad >> 1)*8 + (lane & 7);
    const int b_half = b_quad & 1;

    const __half* csrc[5] = { g_wcI, g_wcI + 16384, g_wcI + 32768,
                              g_wcI + 49152, g_wgo16 };

    const float* xstg = (const float*)(sm + P2_STG);
    const int tl = tid >> 2, qq = tid & 3;

    // first x tile
    {
        int t0 = bid * 64;
        #pragma unroll
        for (int rep = 0; rep < 8; rep++) {
            int it = tid + rep*256;
            int row = it >> 5, q = it & 31;
            CP_ASYNC16(base + P2_STG + row*XROW + q*16,
                       x + (size_t)(t0 + row)*CCH + q*4);
        }
        CP_COMMIT();
        CP_WAIT0();
        __syncthreads();
    }

    for (int tile = bid; tile < NPTILE; tile += NSM) {
        const int t0 = tile * 64;

        // issue B0, B1
        #pragma unroll
        for (int cc = 0; cc < 2; cc++) {
            const __half* s = csrc[cc];
            uint32_t dst = base + P2_B + cc*PTILE;
            #pragma unroll
            for (int rep = 0; rep < 8; rep++) {
                int it = tid + rep*256;
                int row = it >> 4, q = it & 15;
                CP_ASYNC16(dst + row*PROW + q*16, (const char*)(s + row*128) + q*16);
            }
            CP_COMMIT();
        }

        // LN(x) -> split fp16 A
        {
            float v[32];
            float s = 0.f;
            #pragma unroll
            for (int i = 0; i < 8; i++) {
                float4 f = *(const float4*)&xstg[tl*132 + qq*32 + i*4];
                v[i*4]=f.x; v[i*4+1]=f.y; v[i*4+2]=f.z; v[i*4+3]=f.w;
                s += f.x + f.y + f.z + f.w;
            }
            s += __shfl_xor_sync(0xFFFFFFFFu, s, 1);
            s += __shfl_xor_sync(0xFFFFFFFFu, s, 2);
            float m = s * (1.f/128.f);
            float q2 = 0.f;
            #pragma unroll
            for (int i = 0; i < 32; i++) { float d = v[i]-m; q2 += d*d; }
            q2 += __shfl_xor_sync(0xFFFFFFFFu, q2, 1);
            q2 += __shfl_xor_sync(0xFFFFFFFFu, q2, 2);
            float rs = rsqrtf(q2 * (1.f/128.f) + 1e-5f);

            #pragma unroll
            for (int i = 0; i < 16; i++) {
                int k = qq*32 + i*2;
                float v0 = (v[i*2]   - m)*rs*__ldg(&nw[k])   + __ldg(&nb[k]);
                float v1 = (v[i*2+1] - m)*rs*__ldg(&nw[k+1]) + __ldg(&nb[k+1]);
                __half h0 = __float2half_rn(v0);
                __half h1 = __float2half_rn(v1);
                __half2 hh; hh.x = h0; hh.y = h1;
                __half2 ll;
                ll.x = __float2half_rn(v0 - __half2float(h0));
                ll.y = __float2half_rn(v1 - __half2float(h1));
                *(__half2*)(sm + P2_AHI + tl*PROW + k*2) = hh;
                *(__half2*)(sm + P2_ALO + tl*PROW + k*2) = ll;
            }
        }
        __syncthreads();   // A visible; xstg reads done

        // issue next-tile x prefetch (group X)
        if (tile + NSM < NPTILE) {
            int nt0 = (tile + NSM) * 64;
            #pragma unroll
            for (int rep = 0; rep < 8; rep++) {
                int it = tid + rep*256;
                int row = it >> 5, q = it & 31;
                CP_ASYNC16(base + P2_STG + row*XROW + q*16,
                           x + (size_t)(nt0 + row)*CCH + q*4);
            }
        }
        CP_COMMIT();

        // chunk loop: ledger commits B0,B1,X,B2,B3,B4 -> waits 2,2,1,1,0
        #pragma unroll
        for (int c = 0; c < 5; c++) {
            if (c <= 1) CP_WAIT2();
            else if (c <= 3) CP_WAIT1();
            else CP_WAIT0();
            __syncthreads();

            const uint32_t sb = base + P2_B + (c&1)*PTILE;
            float acc[2][4][4];
            #pragma unroll
            for (int mt = 0; mt < 2; mt++)
                #pragma unroll
                for (int nt = 0; nt < 4; nt++)
                    #pragma unroll
                    for (int r = 0; r < 4; r++) acc[mt][nt][r] = 0.f;

            #pragma unroll
            for (int ks = 0; ks < 8; ks++) {
                const uint32_t koff = ks*32;
                uint32_t Ah[2][4], Al[2][4];
                #pragma unroll
                for (int mt = 0; mt < 2; mt++) {
                    uint32_t r = (m_base + mt*16 + a_row)*PROW + koff + a_half*16;
                    ldsm4(Ah[mt], base + P2_AHI + r);
                    ldsm4(Al[mt], base + P2_ALO + r);
                }
                uint32_t Bf[4][2];
                #pragma unroll
                for (int p = 0; p < 2; p++) {
                    uint32_t r = (n_base + p*16 + b_row)*PROW + koff + b_half*16;
                    uint32_t th[4];
                    ldsm4(th, sb + r);
                    Bf[2*p][0]   = th[0]; Bf[2*p][1]   = th[1];
                    Bf[2*p+1][0] = th[2]; Bf[2*p+1][1] = th[3];
                }
                #pragma unroll
                for (int mt = 0; mt < 2; mt++)
                    #pragma unroll
                    for (int nt = 0; nt < 4; nt++) mma16816h(acc[mt][nt], Ah[mt], Bf[nt]);
                #pragma unroll
                for (int mt = 0; mt < 2; mt++)
                    #pragma unroll
                    for (int nt = 0; nt < 4; nt++) mma16816h(acc[mt][nt], Al[mt], Bf[nt]);
            }
            __syncthreads();   // all warps done with buf (c&1)

            // issue B chunk c+2 into buf (c&1)
            if (c <= 2) {
                const __half* s = csrc[c+2];
                uint32_t dst = base + P2_B + (c&1)*PTILE;
                #pragma unroll
                for (int rep = 0; rep < 8; rep++) {
                    int it = tid + rep*256;
                    int row = it >> 4, q = it & 15;
                    CP_ASYNC16(dst + row*PROW + q*16, (const char*)(s + row*128) + q*16);
                }
                CP_COMMIT();
            }

            if (c < 4) {
                // a/b epilogue: gate/proj interleaved in adjacent accumulator lanes
                uint32_t* tp = (uint32_t*)(sm + P2_TP);
                const bool isA = (c < 2);
                #pragma unroll
                for (int mt = 0; mt < 2; mt++) {
                    #pragma unroll
                    for (int rp = 0; rp < 2; rp++) {
                        int t_loc = m_base + mt*16 + rp*8 + (lane >> 2);
                        float mk = isA ? __ldg(&mask[t0 + t_loc]) : 1.f;
                        #pragma unroll
                        for (int nt = 0; nt < 4; nt++) {
                            int c_loc = (n_base >> 1) + nt*4 + (lane & 3);
                            float val = sigmoidf_(acc[mt][nt][rp*2]) * acc[mt][nt][rp*2+1] * mk;
                            tp[c_loc*68 + t_loc] = pack_split16(val);
                        }
                    }
                }
                __syncthreads();

                const int cgl = (c & 1) * 64;
                #pragma unroll
                for (int rep = 0; rep < 8; rep++) {
                    int idx = tid + rep*256;        // 0..2047
                    int cl = idx >> 5, t2 = idx & 31;
                    uint32_t u0 = tp[cl*68 + t2*2];
                    uint32_t u1 = tp[cl*68 + t2*2 + 1];
                    uint32_t hi2 = (u0 & 0xFFFFu) | (u1 << 16);
                    size_t o = ((size_t)(cgl + cl)*NTOK + t0) >> 1;
                    if (isA) {
                        uint32_t lo2 = (u0 >> 16) | (u1 & 0xFFFF0000u);
                        ((uint32_t*)g_ahi)[o + t2] = hi2;
                        ((uint32_t*)g_alo)[o + t2] = lo2;
                    } else {
                        ((uint32_t*)g_bhi)[o + t2] = hi2;
                    }
                }
            } else {
                // out-gate epilogue: token-major sigmoid
                #pragma unroll
                for (int mt = 0; mt < 2; mt++) {
                    #pragma unroll
                    for (int rp = 0; rp < 2; rp++) {
                        int t = t0 + m_base + mt*16 + rp*8 + (lane >> 2);
                        #pragma unroll
                        for (int nt = 0; nt < 4; nt++) {
                            int ch = n_base + nt*8 + (lane & 3)*2;
                            float2 f = make_float2(sigmoidf_(acc[mt][nt][rp*2]),
                                                   sigmoidf_(acc[mt][nt][rp*2+1]));
                            *(float2*)&g_gate[(size_t)t*CCH + ch] = f;
                        }
                    }
                }
            }
        }
    }
}

// ---------------------------------------------------------------------------
// Kernel 2: tri einsum, 2-pass split-fp16, triple-buffered. (unchanged)
// ---------------------------------------------------------------------------
#define ROWB    144
#define TILEB   (128*ROWB)          // 18432
#define CHUNK3  (3*TILEB)           // 55296

__device__ __forceinline__ void tri_load_chunk(
    uint32_t sbuf, const __half* s0, const __half* s1, const __half* s2,
    int kk, int tid)
{
    const __half* srcs[3] = {s0, s1, s2};
    #pragma unroll
    for (int rep = 0; rep < 12; rep++) {
        int it   = tid + rep*256;
        int tile = it >> 10;
        int row  = (it >> 3) & 127;
        int q8   = it & 7;
        const __half* gp = srcs[tile] + (size_t)row*SDIM + kk + q8*8;
        CP_ASYNC16(sbuf + tile*TILEB + row*ROWB + q8*16, gp);
    }
}

__global__ void __launch_bounds__(256) tri_mma_kernel()
{
    extern __shared__ char dynsm[];
    const uint32_t base = smem_u32(dynsm);

    const int tid  = threadIdx.x;
    const int wid  = tid >> 5;
    const int lane = tid & 31;
    const int m_base = (wid >> 2) * 64;
    const int n_base = (wid & 3) * 32;

    const int c  = blockIdx.y;
    const int i0 = (blockIdx.x / 6) * 128;
    const int j0 = (blockIdx.x % 6) * 128;

    const __half* sAh = g_ahi + (size_t)c*NTOK + (size_t)i0*SDIM;
    const __half* sAl = g_alo + (size_t)c*NTOK + (size_t)i0*SDIM;
    const __half* sBh = g_bhi + (size_t)c*NTOK + (size_t)j0*SDIM;

    float acc[4][4][4];
    #pragma unroll
    for (int mt = 0; mt < 4; mt++)
        #pragma unroll
        for (int nt = 0; nt < 4; nt++)
            #pragma unroll
            for (int r = 0; r < 4; r++) acc[mt][nt][r] = 0.f;

    const int a_row  = lane & 15;
    const int a_half = lane >> 4;
    const int b_quad = lane >> 3;
    const int b_row  = (b_quad >> 1) * 8 + (lane & 7);
    const int b_half = b_quad & 1;

    tri_load_chunk(base + 0*CHUNK3, sAh, sAl, sBh, 0,  tid); CP_COMMIT();
    tri_load_chunk(base + 1*CHUNK3, sAh, sAl, sBh, 64, tid); CP_COMMIT();

    for (int n = 0; n < 12; n++) {
        if (n + 2 < 12)
            tri_load_chunk(base + ((n+2)%3)*CHUNK3, sAh, sAl, sBh, (n+2)*64, tid);
        CP_COMMIT();
        CP_WAIT2();
        __syncthreads();

        const uint32_t sb = base + (n%3)*CHUNK3;
        #pragma unroll
        for (int ks = 0; ks < 4; ks++) {
            uint32_t Ah[4][4], Al[4][4], Bh[4][2];
            const uint32_t koff = ks*32;
            #pragma unroll
            for (int mt = 0; mt < 4; mt++) {
                uint32_t r = (m_base + mt*16 + a_row)*ROWB + koff + a_half*16;
                ldsm4(Ah[mt], sb + 0*TILEB + r);
                ldsm4(Al[mt], sb + 1*TILEB + r);
            }
            #pragma unroll
            for (int p = 0; p < 2; p++) {
                uint32_t r = (n_base + p*16 + b_row)*ROWB + koff + b_half*16;
                uint32_t th[4];
                ldsm4(th, sb + 2*TILEB + r);
                Bh[2*p][0]   = th[0]; Bh[2*p][1]   = th[1];
                Bh[2*p+1][0] = th[2]; Bh[2*p+1][1] = th[3];
            }
            #pragma unroll
            for (int mt = 0; mt < 4; mt++)
                #pragma unroll
                for (int nt = 0; nt < 4; nt++)
                    mma16816h(acc[mt][nt], Ah[mt], Bh[nt]);
            #pragma unroll
            for (int mt = 0; mt < 4; mt++)
                #pragma unroll
                for (int nt = 0; nt < 4; nt++)
                    mma16816h(acc[mt][nt], Al[mt], Bh[nt]);
        }
        __syncthreads();
    }

    float* T = g_tri + (size_t)c*NTOK;
    const int er = i0 + m_base + (lane >> 2);
    const int ec2 = j0 + n_base + (lane & 3)*2;
    #pragma unroll
    for (int mt = 0; mt < 4; mt++) {
        #pragma unroll
        for (int nt = 0; nt < 4; nt++) {
            int rr = er + mt*16;
            int cc = ec2 + nt*8;
            *(float2*)&T[(size_t)rr*SDIM + cc]     = make_float2(acc[mt][nt][0], acc[mt][nt][1]);
            *(float2*)&T[(size_t)(rr+8)*SDIM + cc] = make_float2(acc[mt][nt][2], acc[mt][nt][3]);
        }
    }
}

// ---------------------------------------------------------------------------
// Kernel 3: out_persist — 2-pass fp16, 64-token tiles, staged tri+gate.
// ---------------------------------------------------------------------------
#define OV_TRI   0                      // 128 x 272B  (tri [ch][t] f32)
#define OV_G0    34816                  // 64 x 528B   (gate [t][c] f32)
#define OV_G1    (OV_G0 + 33792)
#define OV_AHI   (OV_G1 + 33792)        // 64 x 272B
#define OV_ALO   (OV_AHI + ATILE)
#define OV_B     (OV_ALO + ATILE)       // 1 x PTILE (fp16 hi)
#define OV_SMEM  (OV_B + PTILE)         // 172032
#define NOTILE64 (NTOK/64)              // 9216

__global__ void __launch_bounds__(256) out_persist_kernel(
    const float* __restrict__ now, const float* __restrict__ nob,
    float* __restrict__ out)
{
    extern __shared__ char sm[];
    const uint32_t base = smem_u32(sm);
    const int tid = threadIdx.x;
    const int bid = blockIdx.x;

    // one-time B (wpo^T fp16 hi)
    #pragma unroll
    for (int rep = 0; rep < 8; rep++) {
        int it = tid + rep*256;
        int row = it >> 4, q = it & 15;
        CP_ASYNC16(base + OV_B + row*PROW + q*16,
                   (const char*)(g_wpo16 + row*128) + q*16);
    }
    // first tile: tri + gate
    {
        int t0 = bid * 64;
        #pragma unroll
        for (int rep = 0; rep < 8; rep++) {
            int it = tid + rep*256;
            int ch = it >> 4, q = it & 15;
            CP_ASYNC16(base + OV_TRI + ch*272 + q*16,
                       g_tri + (size_t)ch*NTOK + t0 + q*4);
        }
        #pragma unroll
        for (int rep = 0; rep < 8; rep++) {
            int it = tid + rep*256;
            int row = it >> 5, q = it & 31;
            CP_ASYNC16(base + OV_G0 + row*528 + q*16,
                       g_gate + (size_t)(t0 + row)*CCH + q*4);
        }
    }
    CP_COMMIT();

    const int wid  = tid >> 5;
    const int lane = tid & 31;
    const int m_base = (wid >> 2) * 32;
    const int n_base = (wid & 3) * 32;
    const int a_row  = lane & 15;
    const int a_half = lane >> 4;
    const int b_quad = lane >> 3;
    const int b_row  = (b_quad >> 1)*8 + (lane & 7);
    const int b_half = b_quad & 1;
    const int er = m_base + (lane >> 2);
    const int ec = n_base + (lane & 3)*2;

    const float* trs = (const float*)(sm + OV_TRI);
    const int tl = tid >> 2, qq = tid & 3;

    int ii = 0;
    for (int tile = bid; tile < NOTILE64; tile += NSM, ii++) {
        const int t0 = tile * 64;
        const int gbuf = ii & 1;
        CP_WAIT0();
        __syncthreads();

        // LN over channels -> split fp16 A [t][ch]
        {
            float s = 0.f;
            #pragma unroll 8
            for (int j = 0; j < 32; j++) s += trs[(qq*32 + j)*68 + tl];
            s += __shfl_xor_sync(0xFFFFFFFFu, s, 1);
            s += __shfl_xor_sync(0xFFFFFFFFu, s, 2);
            float m = s * (1.f/128.f);
            float q2 = 0.f;
            #pragma unroll 8
            for (int j = 0; j < 32; j++) {
                float d = trs[(qq*32 + j)*68 + tl] - m;
                q2 += d*d;
            }
            q2 += __shfl_xor_sync(0xFFFFFFFFu, q2, 1);
            q2 += __shfl_xor_sync(0xFFFFFFFFu, q2, 2);
            float rs = rsqrtf(q2 * (1.f/128.f) + 1e-5f);

            #pragma unroll
            for (int j = 0; j < 16; j++) {
                int ch = qq*32 + j*2;
                float v0 = (trs[ch*68 + tl]     - m)*rs*__ldg(&now[ch])   + __ldg(&nob[ch]);
                float v1 = (trs[(ch+1)*68 + tl] - m)*rs*__ldg(&now[ch+1]) + __ldg(&nob[ch+1]);
                __half h0 = __float2half_rn(v0);
                __half h1 = __float2half_rn(v1);
                __half2 hh; hh.x = h0; hh.y = h1;
                __half2 ll;
                ll.x = __float2half_rn(v0 - __half2float(h0));
                ll.y = __float2half_rn(v1 - __half2float(h1));
                *(__half2*)(sm + OV_AHI + tl*PROW + ch*2) = hh;
                *(__half2*)(sm + OV_ALO + tl*PROW + ch*2) = ll;
            }
        }
        __syncthreads();

        // prefetch next tri + gate (other gate buffer)
        if (tile + NSM < NOTILE64) {
            int nt0 = (tile + NSM) * 64;
            #pragma unroll
            for (int rep = 0; rep < 8; rep++) {
                int it = tid + rep*256;
                int ch = it >> 4, q = it & 15;
                CP_ASYNC16(base + OV_TRI + ch*272 + q*16,
                           g_tri + (size_t)ch*NTOK + nt0 + q*4);
            }
            uint32_t gdst = base + (gbuf ? OV_G0 : OV_G1);
            #pragma unroll
            for (int rep = 0; rep < 8; rep++) {
                int it = tid + rep*256;
                int row = it >> 5, q = it & 31;
                CP_ASYNC16(gdst + row*528 + q*16,
                           g_gate + (size_t)(nt0 + row)*CCH + q*4);
            }
        }
        CP_COMMIT();

        float acc[2][4][4];
        #pragma unroll
        for (int mt = 0; mt < 2; mt++)
            #pragma unroll
            for (int nt = 0; nt < 4; nt++)
                #pragma unroll
                for (int r = 0; r < 4; r++) acc[mt][nt][r] = 0.f;

        #pragma unroll
        for (int ks = 0; ks < 8; ks++) {
            const uint32_t koff = ks*32;
            uint32_t Ah[2][4], Al[2][4];
            #pragma unroll
            for (int mt = 0; mt < 2; mt++) {
                uint32_t r = (m_base + mt*16 + a_row)*PROW + koff + a_half*16;
                ldsm4(Ah[mt], base + OV_AHI + r);
                ldsm4(Al[mt], base + OV_ALO + r);
            }
            uint32_t Bf[4][2];
            #pragma unroll
            for (int p = 0; p < 2; p++) {
                uint32_t r = (n_base + p*16 + b_row)*PROW + koff + b_half*16;
                uint32_t th[4];
                ldsm4(th, base + OV_B + r);
                Bf[2*p][0]   = th[0]; Bf[2*p][1]   = th[1];
                Bf[2*p+1][0] = th[2]; Bf[2*p+1][1] = th[3];
            }
            #pragma unroll
            for (int mt = 0; mt < 2; mt++)
                #pragma unroll
                for (int nt = 0; nt < 4; nt++) mma16816h(acc[mt][nt], Ah[mt], Bf[nt]);
            #pragma unroll
            for (int mt = 0; mt < 2; mt++)
                #pragma unroll
                for (int nt = 0; nt < 4; nt++) mma16816h(acc[mt][nt], Al[mt], Bf[nt]);
        }

        const float* gst = (const float*)(sm + (gbuf ? OV_G1 : OV_G0));
        #pragma unroll
        for (int mt = 0; mt < 2; mt++) {
            #pragma unroll
            for (int rp = 0; rp < 2; rp++) {
                int t_loc = er + mt*16 + rp*8;
                #pragma unroll
                for (int nt = 0; nt < 4; nt++) {
                    int cc = ec + nt*8;
                    float2 gg = *(const float2*)&gst[t_loc*132 + cc];
                    float2 o = make_float2(acc[mt][nt][rp*2]   * gg.x,
                                           acc[mt][nt][rp*2+1] * gg.y);
                    *(float2*)&out[(size_t)(t0 + t_loc)*CCH + cc] = o;
                }
            }
        }
        __syncthreads();
    }
}

// ---------------------------------------------------------------------------
extern "C" void kernel_launch(void* const* d_in, const int* in_sizes, int n_in,
                              void* d_out, int out_size)
{
    const float* x    = (const float*)d_in[0];
    const float* mask = (const float*)d_in[1];
    const float* niw  = (const float*)d_in[2];
    const float* nib  = (const float*)d_in[3];
    const float* wgi  = (const float*)d_in[4];
    const float* wpi  = (const float*)d_in[5];
    const float* now  = (const float*)d_in[6];
    const float* nob  = (const float*)d_in[7];
    const float* wgo  = (const float*)d_in[8];
    const float* wpo  = (const float*)d_in[9];
    float* out = (float*)d_out;

    cudaFuncSetAttribute(proj2_kernel,
        cudaFuncAttributeMaxDynamicSharedMemorySize, P2_SMEM);
    cudaFuncSetAttribute(tri_mma_kernel,
        cudaFuncAttributeMaxDynamicSharedMemorySize, 3*CHUNK3);
    cudaFuncSetAttribute(out_persist_kernel,
        cudaFuncAttributeMaxDynamicSharedMemorySize, OV_SMEM);

    prep_w_kernel<<<256, 256>>>(wgi, wpi, wgo, wpo);
    proj2_kernel<<<NSM, 256, P2_SMEM>>>(x, mask, niw, nib);
    tri_mma_kernel<<<dim3(36, 128), 256, 3*CHUNK3>>>();
    out_persist_kernel<<<NSM, 256, OV_SMEM>>>(now, nob, out);
}